// round 4
// baseline (speedup 1.0000x reference)
#include <cuda_runtime.h>
#include <math.h>

#define Tn 2048
#define Dn 1024
#define Hn 16
#define Bn 2
#define Vn 32000
#define Fn 4096
#define NLAYER 4
#define NROWS (Bn*Tn)   // 4096

// ---------------- scratch (static device allocations only) ----------------
__device__ float g_x[(size_t)NROWS*Dn];
__device__ float g_h[(size_t)NROWS*Dn];
__device__ float g_q[(size_t)NROWS*Dn];
__device__ float g_k[(size_t)NROWS*Dn];
__device__ float g_v[(size_t)NROWS*Dn];
__device__ float g_o[(size_t)NROWS*Dn];
__device__ float g_f[(size_t)NROWS*Fn];
__device__ float g_S[(size_t)Bn*Hn*Tn*Tn];   // scores / probs, 536 MB

// ---------------- packed f32x2 helpers ----------------
__device__ __forceinline__ unsigned long long pk2(float a, float b) {
    unsigned long long r;
    asm("mov.b64 %0, {%1, %2};" : "=l"(r) : "f"(a), "f"(b));
    return r;
}
__device__ __forceinline__ void upk2(unsigned long long p, float& a, float& b) {
    asm("mov.b64 {%0, %1}, %2;" : "=f"(a), "=f"(b) : "l"(p));
}
__device__ __forceinline__ void fma2(unsigned long long& c, unsigned long long a,
                                     unsigned long long b) {
    asm("fma.rn.f32x2 %0, %1, %2, %0;" : "+l"(c) : "l"(a), "l"(b));
}

// ---------------- embedding ----------------
__global__ void embed_kernel(const int* __restrict__ ctx,
                             const float* __restrict__ tok,
                             const float* __restrict__ pos,
                             float* __restrict__ x) {
    int row = blockIdx.x;
    int t   = row & (Tn - 1);
    int id  = ctx[row];
    const float4* tp = (const float4*)(tok + (size_t)id * Dn);
    const float4* pp = (const float4*)(pos + (size_t)t * Dn);
    float4* xp = (float4*)(x + (size_t)row * Dn);
    int i = threadIdx.x;                      // 256 threads * float4 = 1024
    float4 a = tp[i], b = pp[i];
    a.x += b.x; a.y += b.y; a.z += b.z; a.w += b.w;
    xp[i] = a;
}

// ---------------- layernorm (one block per row, D=1024) ----------------
__global__ void ln_kernel(const float* __restrict__ x,
                          const float* __restrict__ gam,
                          const float* __restrict__ bet,
                          float* __restrict__ out) {
    __shared__ float ss[8], sq[8];
    int row = blockIdx.x;
    const float* xr = x + (size_t)row * Dn;
    int tid = threadIdx.x, lane = tid & 31, warp = tid >> 5;
    float v[4]; float s = 0.f, q = 0.f;
    #pragma unroll
    for (int i = 0; i < 4; i++) {
        v[i] = xr[tid + 256 * i];
        s += v[i]; q += v[i] * v[i];
    }
    #pragma unroll
    for (int o = 16; o; o >>= 1) {
        s += __shfl_xor_sync(0xffffffffu, s, o);
        q += __shfl_xor_sync(0xffffffffu, q, o);
    }
    if (!lane) { ss[warp] = s; sq[warp] = q; }
    __syncthreads();
    if (tid < 32) {
        float ts = (lane < 8) ? ss[lane] : 0.f;
        float tq = (lane < 8) ? sq[lane] : 0.f;
        #pragma unroll
        for (int o = 4; o; o >>= 1) {
            ts += __shfl_xor_sync(0xffffffffu, ts, o);
            tq += __shfl_xor_sync(0xffffffffu, tq, o);
        }
        if (!lane) { ss[0] = ts; sq[0] = tq; }
    }
    __syncthreads();
    float mean = ss[0] * (1.f / Dn);
    float var  = sq[0] * (1.f / Dn) - mean * mean;
    float r = rsqrtf(var + 1e-5f);
    float* orow = out + (size_t)row * Dn;
    #pragma unroll
    for (int i = 0; i < 4; i++) {
        int c = tid + 256 * i;
        orow[c] = (v[i] - mean) * r * gam[c] + bet[c];
    }
}

// ---------------- SGEMM 128x128x8, FFMA2 inner loop ----------------
// EPI: 0 = none, 1 = +bias, 2 = +bias,relu, 3 = +bias,+res
template <int EPI>
__global__ void __launch_bounds__(256, 2) sgemm_kernel(
    const float* __restrict__ A, const float* __restrict__ Bm,
    const float* __restrict__ bias, const float* __restrict__ res,
    float* __restrict__ C, int N, int Kd) {
    __shared__ float As[8][128];
    __shared__ float Bs[8][128];
    const int tid = threadIdx.x;
    const int tx = tid & 15, ty = tid >> 4;
    const float* Ab = A  + (size_t)blockIdx.y * 128 * Kd;
    const float* Bb = Bm + (size_t)blockIdx.x * 128;
    const int arow = tid >> 1, acol = (tid & 1) << 2;
    const int brow = tid >> 5, bcol = (tid & 31) << 2;

    unsigned long long acc[8][4];
    #pragma unroll
    for (int i = 0; i < 8; i++)
        #pragma unroll
        for (int j = 0; j < 4; j++) acc[i][j] = 0ull;

    for (int k0 = 0; k0 < Kd; k0 += 8) {
        float4 av = *(const float4*)(Ab + (size_t)arow * Kd + (k0 + acol));
        *(float4*)&Bs[brow][bcol] = *(const float4*)(Bb + (size_t)(k0 + brow) * N + bcol);
        As[acol + 0][arow] = av.x;
        As[acol + 1][arow] = av.y;
        As[acol + 2][arow] = av.z;
        As[acol + 3][arow] = av.w;
        __syncthreads();
        #pragma unroll
        for (int kk = 0; kk < 8; kk++) {
            float4 a0 = *(const float4*)&As[kk][ty * 8];
            float4 a1 = *(const float4*)&As[kk][ty * 8 + 4];
            const unsigned long long* bsp =
                (const unsigned long long*)&Bs[kk][tx * 8];
            unsigned long long bp0 = bsp[0], bp1 = bsp[1],
                               bp2 = bsp[2], bp3 = bsp[3];
            float ar[8] = {a0.x, a0.y, a0.z, a0.w, a1.x, a1.y, a1.z, a1.w};
            #pragma unroll
            for (int i = 0; i < 8; i++) {
                unsigned long long ap = pk2(ar[i], ar[i]);
                fma2(acc[i][0], ap, bp0);
                fma2(acc[i][1], ap, bp1);
                fma2(acc[i][2], ap, bp2);
                fma2(acc[i][3], ap, bp3);
            }
        }
        __syncthreads();
    }

    int row0 = blockIdx.y * 128 + ty * 8;
    int col0 = blockIdx.x * 128 + tx * 8;
    float bia[8];
    if (EPI >= 1) {
        float4 c0 = *(const float4*)(bias + col0);
        float4 c1 = *(const float4*)(bias + col0 + 4);
        bia[0]=c0.x; bia[1]=c0.y; bia[2]=c0.z; bia[3]=c0.w;
        bia[4]=c1.x; bia[5]=c1.y; bia[6]=c1.z; bia[7]=c1.w;
    }
    #pragma unroll
    for (int i = 0; i < 8; i++) {
        size_t off = (size_t)(row0 + i) * N + col0;
        float ov[8];
        #pragma unroll
        for (int j2 = 0; j2 < 4; j2++) upk2(acc[i][j2], ov[2*j2], ov[2*j2+1]);
        if (EPI >= 1) {
            #pragma unroll
            for (int j = 0; j < 8; j++) ov[j] += bia[j];
        }
        if (EPI == 2) {
            #pragma unroll
            for (int j = 0; j < 8; j++) ov[j] = fmaxf(ov[j], 0.f);
        }
        if (EPI == 3) {
            float4 r0 = *(const float4*)(res + off);
            float4 r1 = *(const float4*)(res + off + 4);
            ov[0]+=r0.x; ov[1]+=r0.y; ov[2]+=r0.z; ov[3]+=r0.w;
            ov[4]+=r1.x; ov[5]+=r1.y; ov[6]+=r1.z; ov[7]+=r1.w;
        }
        float4 s0 = {ov[0], ov[1], ov[2], ov[3]};
        float4 s1 = {ov[4], ov[5], ov[6], ov[7]};
        *(float4*)(C + off)     = s0;
        *(float4*)(C + off + 4) = s1;
    }
}

// ---------------- attention: S = scale * Q K^T (causal blocks only) ----------
__global__ void attn_scores_kernel(const float* __restrict__ Q,
                                   const float* __restrict__ K,
                                   float* __restrict__ S) {
    int bj = blockIdx.x, bi = blockIdx.y;
    if (bj > bi) return;                       // strictly above diagonal: skip
    int batch = blockIdx.z;                    // b*H + h
    int b = batch >> 4, h = batch & 15;
    __shared__ float Qs[64][68];
    __shared__ float Ks[64][68];
    const float* Qb = Q + ((size_t)(b * Tn + bi * 64)) * Dn + h * 64;
    const float* Kb = K + ((size_t)(b * Tn + bj * 64)) * Dn + h * 64;
    int tid = threadIdx.x;
    for (int l = tid; l < 1024; l += 256) {
        int r = l >> 4, c = (l & 15) << 2;
        *(float4*)&Qs[r][c] = *(const float4*)(Qb + (size_t)r * Dn + c);
        *(float4*)&Ks[r][c] = *(const float4*)(Kb + (size_t)r * Dn + c);
    }
    __syncthreads();
    int tx = tid & 15, ty = tid >> 4;
    float acc[4][4] = {};
    #pragma unroll 4
    for (int e = 0; e < 64; e++) {
        float ar[4], br[4];
        #pragma unroll
        for (int ii = 0; ii < 4; ii++) ar[ii] = Qs[ty * 4 + ii][e];
        #pragma unroll
        for (int jj = 0; jj < 4; jj++) br[jj] = Ks[tx * 4 + jj][e];
        #pragma unroll
        for (int ii = 0; ii < 4; ii++)
            #pragma unroll
            for (int jj = 0; jj < 4; jj++)
                acc[ii][jj] = fmaf(ar[ii], br[jj], acc[ii][jj]);
    }
    const float scale = 0.125f;                // 1/sqrt(64)
    float* Sb = S + ((size_t)batch * Tn + bi * 64) * Tn + (size_t)bj * 64;
    #pragma unroll
    for (int ii = 0; ii < 4; ii++) {
        float4 sv = {acc[ii][0]*scale, acc[ii][1]*scale,
                     acc[ii][2]*scale, acc[ii][3]*scale};
        *(float4*)(Sb + (size_t)(ty * 4 + ii) * Tn + tx * 4) = sv;
    }
}

// ---------------- causal softmax, in place; zeros above diagonal -----------
__global__ void softmax_kernel(float* __restrict__ S) {
    __shared__ float red[8];
    __shared__ float bcast;
    size_t r = blockIdx.x;                     // batch*T + i
    int i = (int)(r & (Tn - 1));
    float* row = S + r * (size_t)Tn;
    int tid = threadIdx.x, lane = tid & 31, warp = tid >> 5;

    float m = -3.4e38f;
    for (int j = tid; j <= i; j += 256) m = fmaxf(m, row[j]);
    #pragma unroll
    for (int o = 16; o; o >>= 1) m = fmaxf(m, __shfl_xor_sync(0xffffffffu, m, o));
    if (!lane) red[warp] = m;
    __syncthreads();
    if (tid < 32) {
        float t = (lane < 8) ? red[lane] : -3.4e38f;
        #pragma unroll
        for (int o = 4; o; o >>= 1) t = fmaxf(t, __shfl_xor_sync(0xffffffffu, t, o));
        if (!lane) bcast = t;
    }
    __syncthreads();
    m = bcast;

    float sum = 0.f;
    for (int j = tid; j <= i; j += 256) {
        float e = __expf(row[j] - m);
        row[j] = e;
        sum += e;
    }
    #pragma unroll
    for (int o = 16; o; o >>= 1) sum += __shfl_xor_sync(0xffffffffu, sum, o);
    __syncthreads();                           // protect red reuse
    if (!lane) red[warp] = sum;
    __syncthreads();
    if (tid < 32) {
        float t = (lane < 8) ? red[lane] : 0.f;
        #pragma unroll
        for (int o = 4; o; o >>= 1) t += __shfl_xor_sync(0xffffffffu, t, o);
        if (!lane) bcast = t;
    }
    __syncthreads();
    float inv = 1.f / bcast;
    for (int j = tid; j < Tn; j += 256) row[j] = (j <= i) ? row[j] * inv : 0.f;
}

// ---------------- O = P @ V (batched, lower-triangular K loop) -------------
__global__ void attn_av_kernel(const float* __restrict__ P,
                               const float* __restrict__ Vm,
                               float* __restrict__ O) {
    int bi = blockIdx.x;
    int batch = blockIdx.y;
    int b = batch >> 4, h = batch & 15;
    __shared__ float Ps[64][68];
    __shared__ float Vs[64][68];
    int tid = threadIdx.x, tx = tid & 15, ty = tid >> 4;
    float acc[4][4] = {};
    const float* Pb = P + ((size_t)batch * Tn + bi * 64) * Tn;
    const float* Vb = Vm + ((size_t)(b * Tn)) * Dn + h * 64;
    for (int jt = 0; jt <= bi; jt++) {
        for (int l = tid; l < 1024; l += 256) {
            int r = l >> 4, c = (l & 15) << 2;
            *(float4*)&Ps[r][c] = *(const float4*)(Pb + (size_t)r * Tn + jt * 64 + c);
            *(float4*)&Vs[r][c] = *(const float4*)(Vb + (size_t)(jt * 64 + r) * Dn + c);
        }
        __syncthreads();
        #pragma unroll 4
        for (int jj = 0; jj < 64; jj++) {
            float ar[4], br[4];
            #pragma unroll
            for (int ii = 0; ii < 4; ii++) ar[ii] = Ps[ty * 4 + ii][jj];
            #pragma unroll
            for (int ee = 0; ee < 4; ee++) br[ee] = Vs[jj][tx * 4 + ee];
            #pragma unroll
            for (int ii = 0; ii < 4; ii++)
                #pragma unroll
                for (int ee = 0; ee < 4; ee++)
                    acc[ii][ee] = fmaf(ar[ii], br[ee], acc[ii][ee]);
        }
        __syncthreads();
    }
    float* Ob = O + ((size_t)(b * Tn + bi * 64)) * Dn + h * 64;
    #pragma unroll
    for (int ii = 0; ii < 4; ii++) {
        float4 sv = {acc[ii][0], acc[ii][1], acc[ii][2], acc[ii][3]};
        *(float4*)(Ob + (size_t)(ty * 4 + ii) * Dn + tx * 4) = sv;
    }
}

// ---------------- launch ----------------
extern "C" void kernel_launch(void* const* d_in, const int* in_sizes, int n_in,
                              void* d_out, int out_size) {
    const int*   ctx  = (const int*)  d_in[0];
    const float* tok  = (const float*)d_in[1];
    const float* pos  = (const float*)d_in[2];
    const float* Wq   = (const float*)d_in[3];
    const float* Wk   = (const float*)d_in[4];
    const float* Wv   = (const float*)d_in[5];
    const float* Wo   = (const float*)d_in[6];
    const float* bo   = (const float*)d_in[7];
    const float* ln1s = (const float*)d_in[8];
    const float* ln1b = (const float*)d_in[9];
    const float* W1   = (const float*)d_in[10];
    const float* b1   = (const float*)d_in[11];
    const float* W2   = (const float*)d_in[12];
    const float* b2   = (const float*)d_in[13];
    const float* ln2s = (const float*)d_in[14];
    const float* ln2b = (const float*)d_in[15];
    const float* lnfs = (const float*)d_in[16];
    const float* lnfb = (const float*)d_in[17];
    const float* Wout = (const float*)d_in[18];
    const float* bout = (const float*)d_in[19];
    float* out = (float*)d_out;

    float *x, *h, *q, *k, *v, *o, *f, *S;
    cudaGetSymbolAddress((void**)&x, g_x);
    cudaGetSymbolAddress((void**)&h, g_h);
    cudaGetSymbolAddress((void**)&q, g_q);
    cudaGetSymbolAddress((void**)&k, g_k);
    cudaGetSymbolAddress((void**)&v, g_v);
    cudaGetSymbolAddress((void**)&o, g_o);
    cudaGetSymbolAddress((void**)&f, g_f);
    cudaGetSymbolAddress((void**)&S, g_S);

    embed_kernel<<<NROWS, 256>>>(ctx, tok, pos, x);

    dim3 gD(Dn / 128, NROWS / 128);     // (8, 32)
    dim3 gF(Fn / 128, NROWS / 128);     // (32, 32)
    dim3 gV(Vn / 128, NROWS / 128);     // (250, 32)
    dim3 gScore(Tn / 64, Tn / 64, Bn * Hn);
    dim3 gAV(Tn / 64, Bn * Hn);

    for (int l = 0; l < NLAYER; l++) {
        const float* wq = Wq + (size_t)l * Dn * Dn;
        const float* wk = Wk + (size_t)l * Dn * Dn;
        const float* wv = Wv + (size_t)l * Dn * Dn;
        const float* wo = Wo + (size_t)l * Dn * Dn;
        const float* w1 = W1 + (size_t)l * Dn * Fn;
        const float* w2 = W2 + (size_t)l * Fn * Dn;

        ln_kernel<<<NROWS, 256>>>(x, ln1s + l * Dn, ln1b + l * Dn, h);
        sgemm_kernel<0><<<gD, 256>>>(h, wq, nullptr, nullptr, q, Dn, Dn);
        sgemm_kernel<0><<<gD, 256>>>(h, wk, nullptr, nullptr, k, Dn, Dn);
        sgemm_kernel<0><<<gD, 256>>>(h, wv, nullptr, nullptr, v, Dn, Dn);

        attn_scores_kernel<<<gScore, 256>>>(q, k, S);
        softmax_kernel<<<Bn * Hn * Tn, 256>>>(S);
        attn_av_kernel<<<gAV, 256>>>(S, v, o);

        // x = x + o @ Wo + bo
        sgemm_kernel<3><<<gD, 256>>>(o, wo, bo + l * Dn, x, x, Dn, Dn);

        ln_kernel<<<NROWS, 256>>>(x, ln2s + l * Dn, ln2b + l * Dn, h);
        // f = relu(h @ W1 + b1)
        sgemm_kernel<2><<<gF, 256>>>(h, w1, b1 + l * Fn, nullptr, f, Fn, Dn);
        // x = x + f @ W2 + b2
        sgemm_kernel<3><<<gD, 256>>>(f, w2, b2 + l * Dn, x, x, Dn, Fn);
    }

    ln_kernel<<<NROWS, 256>>>(x, lnfs, lnfb, h);
    sgemm_kernel<1><<<gV, 256>>>(h, Wout, bout, nullptr, out, Vn, Dn);
}

// round 8
// speedup vs baseline: 2.2021x; 2.2021x over previous
#include <cuda_runtime.h>
#include <cuda_bf16.h>
#include <math.h>
#include <stdint.h>

#define Tn 2048
#define Dn 1024
#define Hn 16
#define Bn 2
#define Vn 32000
#define Fn 4096
#define NLAYER 4
#define NROWS (Bn*Tn)   // 4096
#define KCH 64          // K chunk (bf16) per pipeline stage = 128 bytes/row

// ---------------- scratch (static device allocations only) ----------------
__device__ float g_x[(size_t)NROWS*Dn];
__device__ float g_q[(size_t)NROWS*Dn];
__device__ float g_k[(size_t)NROWS*Dn];
__device__ float g_v[(size_t)NROWS*Dn];
__device__ float g_S[(size_t)Bn*Hn*Tn*Tn];   // scores / probs

__device__ __nv_bfloat16 g_hhi[(size_t)NROWS*Dn];
__device__ __nv_bfloat16 g_hlo[(size_t)NROWS*Dn];
__device__ __nv_bfloat16 g_ohi[(size_t)NROWS*Dn];
__device__ __nv_bfloat16 g_olo[(size_t)NROWS*Dn];
__device__ __nv_bfloat16 g_fhi[(size_t)NROWS*Fn];
__device__ __nv_bfloat16 g_flo[(size_t)NROWS*Fn];

// transposed + split weights: [N, K] K-major bf16
__device__ __nv_bfloat16 g_wqt_hi[(size_t)NLAYER*Dn*Dn];
__device__ __nv_bfloat16 g_wqt_lo[(size_t)NLAYER*Dn*Dn];
__device__ __nv_bfloat16 g_wkt_hi[(size_t)NLAYER*Dn*Dn];
__device__ __nv_bfloat16 g_wkt_lo[(size_t)NLAYER*Dn*Dn];
__device__ __nv_bfloat16 g_wvt_hi[(size_t)NLAYER*Dn*Dn];
__device__ __nv_bfloat16 g_wvt_lo[(size_t)NLAYER*Dn*Dn];
__device__ __nv_bfloat16 g_wot_hi[(size_t)NLAYER*Dn*Dn];
__device__ __nv_bfloat16 g_wot_lo[(size_t)NLAYER*Dn*Dn];
__device__ __nv_bfloat16 g_w1t_hi[(size_t)NLAYER*Dn*Fn];
__device__ __nv_bfloat16 g_w1t_lo[(size_t)NLAYER*Dn*Fn];
__device__ __nv_bfloat16 g_w2t_hi[(size_t)NLAYER*Fn*Dn];
__device__ __nv_bfloat16 g_w2t_lo[(size_t)NLAYER*Fn*Dn];
__device__ __nv_bfloat16 g_woutt_hi[(size_t)Vn*Dn];
__device__ __nv_bfloat16 g_woutt_lo[(size_t)Vn*Dn];

// ---------------- PTX helpers (all baseline sm_80-class; no 'a' features) ---
__device__ __forceinline__ uint32_t smem_u32(const void* p) {
    uint32_t a;
    asm("{ .reg .u64 t; cvta.to.shared.u64 t, %1; cvt.u32.u64 %0, t; }"
        : "=r"(a) : "l"(p));
    return a;
}
__device__ __forceinline__ void cp16(uint32_t s, const void* g) {
    asm volatile("cp.async.cg.shared.global [%0], [%1], 16;"
                 :: "r"(s), "l"(g));
}
__device__ __forceinline__ void cp_commit() {
    asm volatile("cp.async.commit_group;" ::: "memory");
}
template <int Ng> __device__ __forceinline__ void cp_wait() {
    asm volatile("cp.async.wait_group %0;" :: "n"(Ng) : "memory");
}
__device__ __forceinline__ void ldsm4(uint32_t* r, uint32_t addr) {
    asm volatile("ldmatrix.sync.aligned.m8n8.x4.shared.b16 {%0,%1,%2,%3}, [%4];"
                 : "=r"(r[0]), "=r"(r[1]), "=r"(r[2]), "=r"(r[3]) : "r"(addr));
}
__device__ __forceinline__ void mma16816(float* c, const uint32_t* a,
                                         const uint32_t* b) {
    asm volatile(
        "mma.sync.aligned.m16n8k16.row.col.f32.bf16.bf16.f32 "
        "{%0,%1,%2,%3}, {%4,%5,%6,%7}, {%8,%9}, {%0,%1,%2,%3};"
        : "+f"(c[0]), "+f"(c[1]), "+f"(c[2]), "+f"(c[3])
        : "r"(a[0]), "r"(a[1]), "r"(a[2]), "r"(a[3]), "r"(b[0]), "r"(b[1]));
}
__device__ __forceinline__ void split2(float v, __nv_bfloat16& h, __nv_bfloat16& l) {
    h = __float2bfloat16(v);
    l = __float2bfloat16(v - __bfloat162float(h));
}

// ---------------- embedding ----------------
__global__ void embed_kernel(const int* __restrict__ ctx,
                             const float* __restrict__ tok,
                             const float* __restrict__ pos,
                             float* __restrict__ x) {
    int row = blockIdx.x;
    int t   = row & (Tn - 1);
    int id  = ctx[row];
    const float4* tp = (const float4*)(tok + (size_t)id * Dn);
    const float4* pp = (const float4*)(pos + (size_t)t * Dn);
    float4* xp = (float4*)(x + (size_t)row * Dn);
    int i = threadIdx.x;
    float4 a = tp[i], b = pp[i];
    a.x += b.x; a.y += b.y; a.z += b.z; a.w += b.w;
    xp[i] = a;
}

// ---------------- weight transpose + bf16 split: W[K,N] -> Wt[N,K] hi/lo -----
__global__ void wconv_kernel(const float* __restrict__ W,
                             __nv_bfloat16* __restrict__ hi,
                             __nv_bfloat16* __restrict__ lo,
                             int K, int N) {
    __shared__ float t[32][33];
    int tx = threadIdx.x, ty = threadIdx.y;
    int n = blockIdx.x * 32 + tx;
    int k0 = blockIdx.y * 32;
    #pragma unroll
    for (int j = 0; j < 4; j++)
        t[ty + 8 * j][tx] = W[(size_t)(k0 + ty + 8 * j) * N + n];
    __syncthreads();
    int nn0 = blockIdx.x * 32;
    #pragma unroll
    for (int j = 0; j < 4; j++) {
        int nn = nn0 + ty + 8 * j;
        int kk = k0 + tx;
        float v = t[tx][ty + 8 * j];
        __nv_bfloat16 h, l;
        split2(v, h, l);
        hi[(size_t)nn * K + kk] = h;
        lo[(size_t)nn * K + kk] = l;
    }
}

// ---------------- layernorm -> bf16 hi/lo ----------------
__global__ void ln_kernel(const float* __restrict__ x,
                          const float* __restrict__ gam,
                          const float* __restrict__ bet,
                          __nv_bfloat16* __restrict__ hhi,
                          __nv_bfloat16* __restrict__ hlo) {
    __shared__ float ss[8], sq[8];
    int row = blockIdx.x;
    const float* xr = x + (size_t)row * Dn;
    int tid = threadIdx.x, lane = tid & 31, warp = tid >> 5;
    float v[4]; float s = 0.f, q = 0.f;
    #pragma unroll
    for (int i = 0; i < 4; i++) {
        v[i] = xr[tid + 256 * i];
        s += v[i]; q += v[i] * v[i];
    }
    #pragma unroll
    for (int o = 16; o; o >>= 1) {
        s += __shfl_xor_sync(0xffffffffu, s, o);
        q += __shfl_xor_sync(0xffffffffu, q, o);
    }
    if (!lane) { ss[warp] = s; sq[warp] = q; }
    __syncthreads();
    if (tid < 32) {
        float ts = (lane < 8) ? ss[lane] : 0.f;
        float tq = (lane < 8) ? sq[lane] : 0.f;
        #pragma unroll
        for (int o = 4; o; o >>= 1) {
            ts += __shfl_xor_sync(0xffffffffu, ts, o);
            tq += __shfl_xor_sync(0xffffffffu, tq, o);
        }
        if (!lane) { ss[0] = ts; sq[0] = tq; }
    }
    __syncthreads();
    float mean = ss[0] * (1.f / Dn);
    float var  = sq[0] * (1.f / Dn) - mean * mean;
    float r = rsqrtf(var + 1e-5f);
    #pragma unroll
    for (int i = 0; i < 4; i++) {
        int c = tid + 256 * i;
        float y = (v[i] - mean) * r * gam[c] + bet[c];
        __nv_bfloat16 h, l;
        split2(y, h, l);
        hhi[(size_t)row * Dn + c] = h;
        hlo[(size_t)row * Dn + c] = l;
    }
}

// ====== mma.sync bf16 split GEMM: C[M,N] = A[M,K] @ Bt[N,K]^T ===============
// EPI: 0 = none (fp32), 1 = +bias (fp32), 2 = +bias,relu -> bf16 hi/lo,
//      3 = +bias,+res (fp32)
// CTA 128x128, BK=64/stage, 3-stage cp.async pipeline, 8 warps (2M x 4N).
template <int EPI>
__global__ void __launch_bounds__(256, 1) mmagemm(
    const __nv_bfloat16* __restrict__ Ahi, const __nv_bfloat16* __restrict__ Alo,
    const __nv_bfloat16* __restrict__ Bhi, const __nv_bfloat16* __restrict__ Blo,
    const float* __restrict__ bias, const float* __restrict__ res,
    float* __restrict__ C,
    __nv_bfloat16* __restrict__ Chi, __nv_bfloat16* __restrict__ Clo,
    int N, int Kt)
{
    extern __shared__ char dsm[];
    const int tid = threadIdx.x;
    const int lane = tid & 31;
    const int wM = (tid >> 5) >> 2;     // 0..1
    const int wN = (tid >> 5) & 3;      // 0..3
    const int m0 = blockIdx.y * 128;
    const int n0 = blockIdx.x * 128;

    uint32_t sbase = smem_u32(dsm);
    sbase = (sbase + 1023u) & ~1023u;

    const char* pAh = (const char*)(Ahi + (size_t)m0 * Kt);
    const char* pAl = (const char*)(Alo + (size_t)m0 * Kt);
    const char* pBh = (const char*)(Bhi + (size_t)n0 * Kt);
    const char* pBl = (const char*)(Blo + (size_t)n0 * Kt);
    const size_t ldb = (size_t)Kt * 2;   // bytes per row
    const int NS = Kt / KCH;

    // prologue: stages 0 and 1
    #pragma unroll
    for (int ps = 0; ps < 2; ps++) {
        uint32_t sb = sbase + (uint32_t)(ps * 65536);
        size_t kb = (size_t)ps * 128;
        #pragma unroll
        for (int i = 0; i < 4; i++) {
            int id = tid + 256 * i;
            int r = id >> 3, ck = id & 7;
            uint32_t soff = (uint32_t)(r * 128 + ((ck ^ (r & 7)) << 4));
            size_t go = (size_t)r * ldb + kb + (size_t)ck * 16;
            cp16(sb +         soff, pAh + go);
            cp16(sb + 16384 + soff, pAl + go);
            cp16(sb + 32768 + soff, pBh + go);
            cp16(sb + 49152 + soff, pBl + go);
        }
        cp_commit();
    }

    float acc[4][4][4] = {};

    for (int s = 0; s < NS; s++) {
        if (s == NS - 1) cp_wait<0>(); else cp_wait<1>();
        __syncthreads();
        // issue stage s+2 (buffer (s+2)%3 == (s-1)%3, freed by the barrier)
        if (s + 2 < NS) {
            uint32_t sb = sbase + (uint32_t)(((s + 2) % 3) * 65536);
            size_t kb = (size_t)(s + 2) * 128;
            #pragma unroll
            for (int i = 0; i < 4; i++) {
                int id = tid + 256 * i;
                int r = id >> 3, ck = id & 7;
                uint32_t soff = (uint32_t)(r * 128 + ((ck ^ (r & 7)) << 4));
                size_t go = (size_t)r * ldb + kb + (size_t)ck * 16;
                cp16(sb +         soff, pAh + go);
                cp16(sb + 16384 + soff, pAl + go);
                cp16(sb + 32768 + soff, pBh + go);
                cp16(sb + 49152 + soff, pBl + go);
            }
            cp_commit();
        }
        uint32_t base = sbase + (uint32_t)((s % 3) * 65536);
        #pragma unroll
        for (int ks = 0; ks < 4; ks++) {
            uint32_t ah[4][4], al[4][4], bh[4][2], bl[4][2];
            #pragma unroll
            for (int mi = 0; mi < 4; mi++) {
                int r = wM * 64 + mi * 16 + (lane & 15);
                int chunk = ks * 2 + (lane >> 4);
                uint32_t ad = base +
                    (uint32_t)(r * 128 + ((chunk ^ (r & 7)) << 4));
                ldsm4(ah[mi], ad);
                ldsm4(al[mi], ad + 16384u);
            }
            #pragma unroll
            for (int np = 0; np < 2; np++) {
                int g = lane >> 3, rr = lane & 7;
                int nl = wN * 32 + np * 16 + ((g & 2) << 2) + rr;
                int chunk = ks * 2 + (g & 1);
                uint32_t bd = base + 32768u +
                    (uint32_t)(nl * 128 + ((chunk ^ (nl & 7)) << 4));
                uint32_t t0[4], t1[4];
                ldsm4(t0, bd);
                ldsm4(t1, bd + 16384u);
                bh[np*2][0] = t0[0]; bh[np*2][1] = t0[1];
                bh[np*2+1][0] = t0[2]; bh[np*2+1][1] = t0[3];
                bl[np*2][0] = t1[0]; bl[np*2][1] = t1[1];
                bl[np*2+1][0] = t1[2]; bl[np*2+1][1] = t1[3];
            }
            #pragma unroll
            for (int mi = 0; mi < 4; mi++)
                #pragma unroll
                for (int nj = 0; nj < 4; nj++) {
                    mma16816(acc[mi][nj], ah[mi], bh[nj]);
                    mma16816(acc[mi][nj], ah[mi], bl[nj]);
                    mma16816(acc[mi][nj], al[mi], bh[nj]);
                }
        }
    }

    // ---------------- epilogue from register accumulators ----------------
    const int rb = m0 + wM * 64 + (lane >> 2);
    const int cb = n0 + wN * 32 + (lane & 3) * 2;
    #pragma unroll
    for (int mi = 0; mi < 4; mi++) {
        #pragma unroll
        for (int nj = 0; nj < 4; nj++) {
            int r0 = rb + mi * 16;
            int c = cb + nj * 8;
            float* a = acc[mi][nj];
            float b0 = 0.f, b1 = 0.f;
            if (EPI >= 1) {
                float2 bv = *(const float2*)(bias + c);
                b0 = bv.x; b1 = bv.y;
            }
            float v0 = a[0] + b0, v1 = a[1] + b1;
            float v2 = a[2] + b0, v3 = a[3] + b1;
            if (EPI == 2) {
                v0 = fmaxf(v0, 0.f); v1 = fmaxf(v1, 0.f);
                v2 = fmaxf(v2, 0.f); v3 = fmaxf(v3, 0.f);
                __nv_bfloat16 h0, l0, h1, l1;
                split2(v0, h0, l0); split2(v1, h1, l1);
                __nv_bfloat162 ph; ph.x = h0; ph.y = h1;
                __nv_bfloat162 pl; pl.x = l0; pl.y = l1;
                *(__nv_bfloat162*)(Chi + (size_t)r0 * N + c) = ph;
                *(__nv_bfloat162*)(Clo + (size_t)r0 * N + c) = pl;
                split2(v2, h0, l0); split2(v3, h1, l1);
                ph.x = h0; ph.y = h1; pl.x = l0; pl.y = l1;
                *(__nv_bfloat162*)(Chi + (size_t)(r0 + 8) * N + c) = ph;
                *(__nv_bfloat162*)(Clo + (size_t)(r0 + 8) * N + c) = pl;
            } else {
                if (EPI == 3) {
                    float2 r1 = *(const float2*)(res + (size_t)r0 * N + c);
                    float2 r2 = *(const float2*)(res + (size_t)(r0 + 8) * N + c);
                    v0 += r1.x; v1 += r1.y; v2 += r2.x; v3 += r2.y;
                }
                float2 o1 = {v0, v1}, o2 = {v2, v3};
                *(float2*)(C + (size_t)r0 * N + c) = o1;
                *(float2*)(C + (size_t)(r0 + 8) * N + c) = o2;
            }
        }
    }
}

// ---------------- attention: S = scale * Q K^T (causal blocks only) ----------
__global__ void attn_scores_kernel(const float* __restrict__ Q,
                                   const float* __restrict__ K,
                                   float* __restrict__ S) {
    int bj = blockIdx.x, bi = blockIdx.y;
    if (bj > bi) return;
    int batch = blockIdx.z;
    int b = batch >> 4, h = batch & 15;
    __shared__ float Qs[64][68];
    __shared__ float Ks[64][68];
    const float* Qb = Q + ((size_t)(b * Tn + bi * 64)) * Dn + h * 64;
    const float* Kb = K + ((size_t)(b * Tn + bj * 64)) * Dn + h * 64;
    int tid = threadIdx.x;
    for (int l = tid; l < 1024; l += 256) {
        int r = l >> 4, c = (l & 15) << 2;
        *(float4*)&Qs[r][c] = *(const float4*)(Qb + (size_t)r * Dn + c);
        *(float4*)&Ks[r][c] = *(const float4*)(Kb + (size_t)r * Dn + c);
    }
    __syncthreads();
    int tx = tid & 15, ty = tid >> 4;
    float acc[4][4] = {};
    #pragma unroll 4
    for (int e = 0; e < 64; e++) {
        float ar[4], br[4];
        #pragma unroll
        for (int ii = 0; ii < 4; ii++) ar[ii] = Qs[ty * 4 + ii][e];
        #pragma unroll
        for (int jj = 0; jj < 4; jj++) br[jj] = Ks[tx * 4 + jj][e];
        #pragma unroll
        for (int ii = 0; ii < 4; ii++)
            #pragma unroll
            for (int jj = 0; jj < 4; jj++)
                acc[ii][jj] = fmaf(ar[ii], br[jj], acc[ii][jj]);
    }
    const float scale = 0.125f;
    float* Sb = S + ((size_t)batch * Tn + bi * 64) * Tn + (size_t)bj * 64;
    #pragma unroll
    for (int ii = 0; ii < 4; ii++) {
        float4 sv = {acc[ii][0]*scale, acc[ii][1]*scale,
                     acc[ii][2]*scale, acc[ii][3]*scale};
        *(float4*)(Sb + (size_t)(ty * 4 + ii) * Tn + tx * 4) = sv;
    }
}

// ---------------- causal softmax in place (zeroes only diag-block tail) ------
__global__ void softmax_kernel(float* __restrict__ S) {
    __shared__ float red[8];
    __shared__ float bcast;
    size_t r = blockIdx.x;
    int i = (int)(r & (Tn - 1));
    float* row = S + r * (size_t)Tn;
    int tid = threadIdx.x, lane = tid & 31, warp = tid >> 5;

    float m = -3.4e38f;
    for (int j = tid; j <= i; j += 256) m = fmaxf(m, row[j]);
    #pragma unroll
    for (int o = 16; o; o >>= 1) m = fmaxf(m, __shfl_xor_sync(0xffffffffu, m, o));
    if (!lane) red[warp] = m;
    __syncthreads();
    if (tid < 32) {
        float t = (lane < 8) ? red[lane] : -3.4e38f;
        #pragma unroll
        for (int o = 4; o; o >>= 1) t = fmaxf(t, __shfl_xor_sync(0xffffffffu, t, o));
        if (!lane) bcast = t;
    }
    __syncthreads();
    m = bcast;

    float sum = 0.f;
    for (int j = tid; j <= i; j += 256) {
        float e = __expf(row[j] - m);
        row[j] = e;
        sum += e;
    }
    #pragma unroll
    for (int o = 16; o; o >>= 1) sum += __shfl_xor_sync(0xffffffffu, sum, o);
    __syncthreads();
    if (!lane) red[warp] = sum;
    __syncthreads();
    if (tid < 32) {
        float t = (lane < 8) ? red[lane] : 0.f;
        #pragma unroll
        for (int o = 4; o; o >>= 1) t += __shfl_xor_sync(0xffffffffu, t, o);
        if (!lane) bcast = t;
    }
    __syncthreads();
    float inv = 1.f / bcast;
    int jend = ((i >> 6) + 1) << 6;       // AV only reads blocks jt <= i>>6
    for (int j = tid; j < jend; j += 256) {
        float val = (j <= i) ? row[j] * inv : 0.f;
        row[j] = val;
    }
}

// ---------------- O = P @ V -> bf16 hi/lo ----------------
__global__ void attn_av_kernel(const float* __restrict__ P,
                               const float* __restrict__ Vm,
                               __nv_bfloat16* __restrict__ Ohi,
                               __nv_bfloat16* __restrict__ Olo) {
    int bi = blockIdx.x;
    int batch = blockIdx.y;
    int b = batch >> 4, h = batch & 15;
    __shared__ float Ps[64][68];
    __shared__ float Vs[64][68];
    int tid = threadIdx.x, tx = tid & 15, ty = tid >> 4;
    float acc[4][4] = {};
    const float* Pb = P + ((size_t)batch * Tn + bi * 64) * Tn;
    const float* Vb = Vm + ((size_t)(b * Tn)) * Dn + h * 64;
    for (int jt = 0; jt <= bi; jt++) {
        for (int l = tid; l < 1024; l += 256) {
            int r = l >> 4, c = (l & 15) << 2;
            *(float4*)&Ps[r][c] = *(const float4*)(Pb + (size_t)r * Tn + jt * 64 + c);
            *(float4*)&Vs[r][c] = *(const float4*)(Vb + (size_t)(jt * 64 + r) * Dn + c);
        }
        __syncthreads();
        #pragma unroll 4
        for (int jj = 0; jj < 64; jj++) {
            float ar[4], br[4];
            #pragma unroll
            for (int ii = 0; ii < 4; ii++) ar[ii] = Ps[ty * 4 + ii][jj];
            #pragma unroll
            for (int ee = 0; ee < 4; ee++) br[ee] = Vs[jj][tx * 4 + ee];
            #pragma unroll
            for (int ii = 0; ii < 4; ii++)
                #pragma unroll
                for (int ee = 0; ee < 4; ee++)
                    acc[ii][ee] = fmaf(ar[ii], br[ee], acc[ii][ee]);
        }
        __syncthreads();
    }
    size_t ob = ((size_t)(b * Tn + bi * 64)) * Dn + h * 64;
    #pragma unroll
    for (int ii = 0; ii < 4; ii++) {
        size_t off = ob + (size_t)(ty * 4 + ii) * Dn + tx * 4;
        __nv_bfloat16 h0, l0, h1, l1, h2, l2, h3, l3;
        split2(acc[ii][0], h0, l0);
        split2(acc[ii][1], h1, l1);
        split2(acc[ii][2], h2, l2);
        split2(acc[ii][3], h3, l3);
        __nv_bfloat162 p01; p01.x = h0; p01.y = h1;
        __nv_bfloat162 p23; p23.x = h2; p23.y = h3;
        __nv_bfloat162 q01; q01.x = l0; q01.y = l1;
        __nv_bfloat162 q23; q23.x = l2; q23.y = l3;
        *(__nv_bfloat162*)(Ohi + off)     = p01;
        *(__nv_bfloat162*)(Ohi + off + 2) = p23;
        *(__nv_bfloat162*)(Olo + off)     = q01;
        *(__nv_bfloat162*)(Olo + off + 2) = q23;
    }
}

// ---------------- launch ----------------
#define SMEM_DYN (1024 + 3 * 65536)

extern "C" void kernel_launch(void* const* d_in, const int* in_sizes, int n_in,
                              void* d_out, int out_size) {
    const int*   ctx  = (const int*)  d_in[0];
    const float* tok  = (const float*)d_in[1];
    const float* pos  = (const float*)d_in[2];
    const float* Wq   = (const float*)d_in[3];
    const float* Wk   = (const float*)d_in[4];
    const float* Wv   = (const float*)d_in[5];
    const float* Wo   = (const float*)d_in[6];
    const float* bo   = (const float*)d_in[7];
    const float* ln1s = (const float*)d_in[8];
    const float* ln1b = (const float*)d_in[9];
    const float* W1   = (const float*)d_in[10];
    const float* b1   = (const float*)d_in[11];
    const float* W2   = (const float*)d_in[12];
    const float* b2   = (const float*)d_in[13];
    const float* ln2s = (const float*)d_in[14];
    const float* ln2b = (const float*)d_in[15];
    const float* lnfs = (const float*)d_in[16];
    const float* lnfb = (const float*)d_in[17];
    const float* Wout = (const float*)d_in[18];
    const float* bout = (const float*)d_in[19];
    float* out = (float*)d_out;

    float *x, *q, *k, *v, *S;
    __nv_bfloat16 *hhi, *hlo, *ohi, *olo, *fhi, *flo;
    __nv_bfloat16 *wqh, *wql, *wkh, *wkl, *wvh, *wvl, *woh, *wol;
    __nv_bfloat16 *w1h, *w1l, *w2h, *w2l, *wouth, *woutl;
    cudaGetSymbolAddress((void**)&x, g_x);
    cudaGetSymbolAddress((void**)&q, g_q);
    cudaGetSymbolAddress((void**)&k, g_k);
    cudaGetSymbolAddress((void**)&v, g_v);
    cudaGetSymbolAddress((void**)&S, g_S);
    cudaGetSymbolAddress((void**)&hhi, g_hhi);
    cudaGetSymbolAddress((void**)&hlo, g_hlo);
    cudaGetSymbolAddress((void**)&ohi, g_ohi);
    cudaGetSymbolAddress((void**)&olo, g_olo);
    cudaGetSymbolAddress((void**)&fhi, g_fhi);
    cudaGetSymbolAddress((void**)&flo, g_flo);
    cudaGetSymbolAddress((void**)&wqh, g_wqt_hi);
    cudaGetSymbolAddress((void**)&wql, g_wqt_lo);
    cudaGetSymbolAddress((void**)&wkh, g_wkt_hi);
    cudaGetSymbolAddress((void**)&wkl, g_wkt_lo);
    cudaGetSymbolAddress((void**)&wvh, g_wvt_hi);
    cudaGetSymbolAddress((void**)&wvl, g_wvt_lo);
    cudaGetSymbolAddress((void**)&woh, g_wot_hi);
    cudaGetSymbolAddress((void**)&wol, g_wot_lo);
    cudaGetSymbolAddress((void**)&w1h, g_w1t_hi);
    cudaGetSymbolAddress((void**)&w1l, g_w1t_lo);
    cudaGetSymbolAddress((void**)&w2h, g_w2t_hi);
    cudaGetSymbolAddress((void**)&w2l, g_w2t_lo);
    cudaGetSymbolAddress((void**)&wouth, g_woutt_hi);
    cudaGetSymbolAddress((void**)&woutl, g_woutt_lo);

    cudaFuncSetAttribute(mmagemm<0>, cudaFuncAttributeMaxDynamicSharedMemorySize, SMEM_DYN);
    cudaFuncSetAttribute(mmagemm<1>, cudaFuncAttributeMaxDynamicSharedMemorySize, SMEM_DYN);
    cudaFuncSetAttribute(mmagemm<2>, cudaFuncAttributeMaxDynamicSharedMemorySize, SMEM_DYN);
    cudaFuncSetAttribute(mmagemm<3>, cudaFuncAttributeMaxDynamicSharedMemorySize, SMEM_DYN);

    // weight prep (runs inside the graph; deterministic)
    {
        dim3 blk(32, 8);
        dim3 gDD(Dn / 32, Dn / 32);
        dim3 gDF(Fn / 32, Dn / 32);   // W1 [D,4D] -> [4D,D]
        dim3 gFD(Dn / 32, Fn / 32);   // W2 [4D,D] -> [D,4D]
        dim3 gDV(Vn / 32, Dn / 32);
        for (int l = 0; l < NLAYER; l++) {
            size_t dd = (size_t)l * Dn * Dn;
            size_t df = (size_t)l * Dn * Fn;
            wconv_kernel<<<gDD, blk>>>(Wq + dd, wqh + dd, wql + dd, Dn, Dn);
            wconv_kernel<<<gDD, blk>>>(Wk + dd, wkh + dd, wkl + dd, Dn, Dn);
            wconv_kernel<<<gDD, blk>>>(Wv + dd, wvh + dd, wvl + dd, Dn, Dn);
            wconv_kernel<<<gDD, blk>>>(Wo + dd, woh + dd, wol + dd, Dn, Dn);
            wconv_kernel<<<gDF, blk>>>(W1 + df, w1h + df, w1l + df, Dn, Fn);
            wconv_kernel<<<gFD, blk>>>(W2 + df, w2h + df, w2l + df, Fn, Dn);
        }
        wconv_kernel<<<gDV, blk>>>(Wout, wouth, woutl, Dn, Vn);
    }

    embed_kernel<<<NROWS, 256>>>(ctx, tok, pos, x);

    dim3 gD(Dn / 128, NROWS / 128);     // (8, 32)
    dim3 gF(Fn / 128, NROWS / 128);     // (32, 32)
    dim3 gV(Vn / 128, NROWS / 128);     // (250, 32)
    dim3 gScore(Tn / 64, Tn / 64, Bn * Hn);
    dim3 gAV(Tn / 64, Bn * Hn);

    for (int l = 0; l < NLAYER; l++) {
        size_t dd = (size_t)l * Dn * Dn;
        size_t df = (size_t)l * Dn * Fn;

        ln_kernel<<<NROWS, 256>>>(x, ln1s + l * Dn, ln1b + l * Dn, hhi, hlo);
        mmagemm<0><<<gD, 256, SMEM_DYN>>>(hhi, hlo, wqh + dd, wql + dd,
                                          nullptr, nullptr, q, nullptr, nullptr, Dn, Dn);
        mmagemm<0><<<gD, 256, SMEM_DYN>>>(hhi, hlo, wkh + dd, wkl + dd,
                                          nullptr, nullptr, k, nullptr, nullptr, Dn, Dn);
        mmagemm<0><<<gD, 256, SMEM_DYN>>>(hhi, hlo, wvh + dd, wvl + dd,
                                          nullptr, nullptr, v, nullptr, nullptr, Dn, Dn);

        attn_scores_kernel<<<gScore, 256>>>(q, k, S);
        softmax_kernel<<<Bn * Hn * Tn, 256>>>(S);
        attn_av_kernel<<<gAV, 256>>>(S, v, ohi, olo);

        // x = x + o @ Wo + bo
        mmagemm<3><<<gD, 256, SMEM_DYN>>>(ohi, olo, woh + dd, wol + dd,
                                          bo + l * Dn, x, x, nullptr, nullptr, Dn, Dn);

        ln_kernel<<<NROWS, 256>>>(x, ln2s + l * Dn, ln2b + l * Dn, hhi, hlo);
        // f = relu(h @ W1 + b1) -> bf16 hi/lo
        mmagemm<2><<<gF, 256, SMEM_DYN>>>(hhi, hlo, w1h + df, w1l + df,
                                          b1 + l * Fn, nullptr, nullptr, fhi, flo, Fn, Dn);
        // x = x + f @ W2 + b2
        mmagemm<3><<<gD, 256, SMEM_DYN>>>(fhi, flo, w2h + df, w2l + df,
                                          b2 + l * Dn, x, x, nullptr, nullptr, Dn, Fn);
    }

    ln_kernel<<<NROWS, 256>>>(x, lnfs, lnfb, hhi, hlo);
    mmagemm<1><<<gV, 256, SMEM_DYN>>>(hhi, hlo, wouth, woutl,
                                      bout, nullptr, out, nullptr, nullptr, Vn, Dn);
}

// round 11
// speedup vs baseline: 3.0515x; 1.3857x over previous
#include <cuda_runtime.h>
#include <cuda_bf16.h>
#include <math.h>
#include <stdint.h>

#define Tn 2048
#define Dn 1024
#define Hn 16
#define Bn 2
#define Vn 32000
#define Fn 4096
#define NLAYER 4
#define NROWS (Bn*Tn)   // 4096
#define KCH 64          // K chunk (bf16) per pipeline stage = 128 bytes/row

// ---------------- scratch (static device allocations only) ----------------
__device__ float g_x[(size_t)NROWS*Dn];
__device__ float g_S[(size_t)Bn*Hn*Tn*Tn];          // fp32 scores / exp
__device__ __nv_bfloat16 g_phi[(size_t)Bn*Hn*Tn*Tn]; // probs hi
__device__ __nv_bfloat16 g_plo[(size_t)Bn*Hn*Tn*Tn]; // probs lo

__device__ __nv_bfloat16 g_hhi[(size_t)NROWS*Dn];
__device__ __nv_bfloat16 g_hlo[(size_t)NROWS*Dn];
__device__ __nv_bfloat16 g_qhi[(size_t)NROWS*Dn];
__device__ __nv_bfloat16 g_qlo[(size_t)NROWS*Dn];
__device__ __nv_bfloat16 g_khi[(size_t)NROWS*Dn];
__device__ __nv_bfloat16 g_klo[(size_t)NROWS*Dn];
__device__ __nv_bfloat16 g_vhi[(size_t)NROWS*Dn];
__device__ __nv_bfloat16 g_vlo[(size_t)NROWS*Dn];
__device__ __nv_bfloat16 g_ohi[(size_t)NROWS*Dn];
__device__ __nv_bfloat16 g_olo[(size_t)NROWS*Dn];
__device__ __nv_bfloat16 g_fhi[(size_t)NROWS*Fn];
__device__ __nv_bfloat16 g_flo[(size_t)NROWS*Fn];

// transposed + split weights: [N, K] K-major bf16
__device__ __nv_bfloat16 g_wqt_hi[(size_t)NLAYER*Dn*Dn];
__device__ __nv_bfloat16 g_wqt_lo[(size_t)NLAYER*Dn*Dn];
__device__ __nv_bfloat16 g_wkt_hi[(size_t)NLAYER*Dn*Dn];
__device__ __nv_bfloat16 g_wkt_lo[(size_t)NLAYER*Dn*Dn];
__device__ __nv_bfloat16 g_wvt_hi[(size_t)NLAYER*Dn*Dn];
__device__ __nv_bfloat16 g_wvt_lo[(size_t)NLAYER*Dn*Dn];
__device__ __nv_bfloat16 g_wot_hi[(size_t)NLAYER*Dn*Dn];
__device__ __nv_bfloat16 g_wot_lo[(size_t)NLAYER*Dn*Dn];
__device__ __nv_bfloat16 g_w1t_hi[(size_t)NLAYER*Dn*Fn];
__device__ __nv_bfloat16 g_w1t_lo[(size_t)NLAYER*Dn*Fn];
__device__ __nv_bfloat16 g_w2t_hi[(size_t)NLAYER*Fn*Dn];
__device__ __nv_bfloat16 g_w2t_lo[(size_t)NLAYER*Fn*Dn];
__device__ __nv_bfloat16 g_woutt_hi[(size_t)Vn*Dn];
__device__ __nv_bfloat16 g_woutt_lo[(size_t)Vn*Dn];

// ---------------- PTX helpers (baseline sm_80-class only) ----------------
__device__ __forceinline__ uint32_t smem_u32(const void* p) {
    uint32_t a;
    asm("{ .reg .u64 t; cvta.to.shared.u64 t, %1; cvt.u32.u64 %0, t; }"
        : "=r"(a) : "l"(p));
    return a;
}
__device__ __forceinline__ void cp16(uint32_t s, const void* g) {
    asm volatile("cp.async.cg.shared.global [%0], [%1], 16;"
                 :: "r"(s), "l"(g));
}
__device__ __forceinline__ void cp_commit() {
    asm volatile("cp.async.commit_group;" ::: "memory");
}
template <int Ng> __device__ __forceinline__ void cp_wait() {
    asm volatile("cp.async.wait_group %0;" :: "n"(Ng) : "memory");
}
__device__ __forceinline__ void ldsm4(uint32_t* r, uint32_t addr) {
    asm volatile("ldmatrix.sync.aligned.m8n8.x4.shared.b16 {%0,%1,%2,%3}, [%4];"
                 : "=r"(r[0]), "=r"(r[1]), "=r"(r[2]), "=r"(r[3]) : "r"(addr));
}
__device__ __forceinline__ void ldsm4t(uint32_t* r, uint32_t addr) {
    asm volatile("ldmatrix.sync.aligned.m8n8.x4.trans.shared.b16 {%0,%1,%2,%3}, [%4];"
                 : "=r"(r[0]), "=r"(r[1]), "=r"(r[2]), "=r"(r[3]) : "r"(addr));
}
__device__ __forceinline__ void mma16816(float* c, const uint32_t* a,
                                         const uint32_t* b) {
    asm volatile(
        "mma.sync.aligned.m16n8k16.row.col.f32.bf16.bf16.f32 "
        "{%0,%1,%2,%3}, {%4,%5,%6,%7}, {%8,%9}, {%0,%1,%2,%3};"
        : "+f"(c[0]), "+f"(c[1]), "+f"(c[2]), "+f"(c[3])
        : "r"(a[0]), "r"(a[1]), "r"(a[2]), "r"(a[3]), "r"(b[0]), "r"(b[1]));
}
__device__ __forceinline__ void split2(float v, __nv_bfloat16& h, __nv_bfloat16& l) {
    h = __float2bfloat16(v);
    l = __float2bfloat16(v - __bfloat162float(h));
}
// swizzles: 128B rows (8 x 16B chunks) and 256B rows (16 chunks)
#define SWZ128(c, r) (((c) ^ ((r) & 7)) << 4)
#define SWZ256(c, r) (((((c) ^ ((r) & 7)) & 7) | ((c) & 8)) << 4)

// ---------------- embedding ----------------
__global__ void embed_kernel(const int* __restrict__ ctx,
                             const float* __restrict__ tok,
                             const float* __restrict__ pos,
                             float* __restrict__ x) {
    int row = blockIdx.x;
    int t   = row & (Tn - 1);
    int id  = ctx[row];
    const float4* tp = (const float4*)(tok + (size_t)id * Dn);
    const float4* pp = (const float4*)(pos + (size_t)t * Dn);
    float4* xp = (float4*)(x + (size_t)row * Dn);
    int i = threadIdx.x;
    float4 a = tp[i], b = pp[i];
    a.x += b.x; a.y += b.y; a.z += b.z; a.w += b.w;
    xp[i] = a;
}

// ---------------- weight transpose + bf16 split: W[K,N] -> Wt[N,K] hi/lo -----
__global__ void wconv_kernel(const float* __restrict__ W,
                             __nv_bfloat16* __restrict__ hi,
                             __nv_bfloat16* __restrict__ lo,
                             int K, int N) {
    __shared__ float t[32][33];
    int tx = threadIdx.x, ty = threadIdx.y;
    int n = blockIdx.x * 32 + tx;
    int k0 = blockIdx.y * 32;
    #pragma unroll
    for (int j = 0; j < 4; j++)
        t[ty + 8 * j][tx] = W[(size_t)(k0 + ty + 8 * j) * N + n];
    __syncthreads();
    int nn0 = blockIdx.x * 32;
    #pragma unroll
    for (int j = 0; j < 4; j++) {
        int nn = nn0 + ty + 8 * j;
        int kk = k0 + tx;
        float v = t[tx][ty + 8 * j];
        __nv_bfloat16 h, l;
        split2(v, h, l);
        hi[(size_t)nn * K + kk] = h;
        lo[(size_t)nn * K + kk] = l;
    }
}

// ---------------- layernorm -> bf16 hi/lo ----------------
__global__ void ln_kernel(const float* __restrict__ x,
                          const float* __restrict__ gam,
                          const float* __restrict__ bet,
                          __nv_bfloat16* __restrict__ hhi,
                          __nv_bfloat16* __restrict__ hlo) {
    __shared__ float ss[8], sq[8];
    int row = blockIdx.x;
    const float* xr = x + (size_t)row * Dn;
    int tid = threadIdx.x, lane = tid & 31, warp = tid >> 5;
    float v[4]; float s = 0.f, q = 0.f;
    #pragma unroll
    for (int i = 0; i < 4; i++) {
        v[i] = xr[tid + 256 * i];
        s += v[i]; q += v[i] * v[i];
    }
    #pragma unroll
    for (int o = 16; o; o >>= 1) {
        s += __shfl_xor_sync(0xffffffffu, s, o);
        q += __shfl_xor_sync(0xffffffffu, q, o);
    }
    if (!lane) { ss[warp] = s; sq[warp] = q; }
    __syncthreads();
    if (tid < 32) {
        float ts = (lane < 8) ? ss[lane] : 0.f;
        float tq = (lane < 8) ? sq[lane] : 0.f;
        #pragma unroll
        for (int o = 4; o; o >>= 1) {
            ts += __shfl_xor_sync(0xffffffffu, ts, o);
            tq += __shfl_xor_sync(0xffffffffu, tq, o);
        }
        if (!lane) { ss[0] = ts; sq[0] = tq; }
    }
    __syncthreads();
    float mean = ss[0] * (1.f / Dn);
    float var  = sq[0] * (1.f / Dn) - mean * mean;
    float r = rsqrtf(var + 1e-5f);
    #pragma unroll
    for (int i = 0; i < 4; i++) {
        int c = tid + 256 * i;
        float y = (v[i] - mean) * r * gam[c] + bet[c];
        __nv_bfloat16 h, l;
        split2(y, h, l);
        hhi[(size_t)row * Dn + c] = h;
        hlo[(size_t)row * Dn + c] = l;
    }
}

// ====== mma.sync bf16 split GEMM: C[M,N] = A[M,K] @ Bt[N,K]^T ===============
// EPI: 1 = +bias (fp32), 2 = +bias,relu -> bf16 hi/lo,
//      3 = +bias,+res (fp32), 4 = plain -> bf16 hi/lo
template <int EPI>
__global__ void __launch_bounds__(256, 1) mmagemm(
    const __nv_bfloat16* __restrict__ Ahi, const __nv_bfloat16* __restrict__ Alo,
    const __nv_bfloat16* __restrict__ Bhi, const __nv_bfloat16* __restrict__ Blo,
    const float* __restrict__ bias, const float* __restrict__ res,
    float* __restrict__ C,
    __nv_bfloat16* __restrict__ Chi, __nv_bfloat16* __restrict__ Clo,
    int N, int Kt)
{
    extern __shared__ char dsm[];
    const int tid = threadIdx.x;
    const int lane = tid & 31;
    const int wM = (tid >> 5) >> 2;     // 0..1
    const int wN = (tid >> 5) & 3;      // 0..3
    const int m0 = blockIdx.y * 128;
    const int n0 = blockIdx.x * 128;

    uint32_t sbase = smem_u32(dsm);
    sbase = (sbase + 1023u) & ~1023u;

    const char* pAh = (const char*)(Ahi + (size_t)m0 * Kt);
    const char* pAl = (const char*)(Alo + (size_t)m0 * Kt);
    const char* pBh = (const char*)(Bhi + (size_t)n0 * Kt);
    const char* pBl = (const char*)(Blo + (size_t)n0 * Kt);
    const size_t ldb = (size_t)Kt * 2;   // bytes per row
    const int NS = Kt / KCH;

    // prologue: stages 0 and 1
    #pragma unroll
    for (int ps = 0; ps < 2; ps++) {
        uint32_t sb = sbase + (uint32_t)(ps * 65536);
        size_t kb = (size_t)ps * 128;
        #pragma unroll
        for (int i = 0; i < 4; i++) {
            int id = tid + 256 * i;
            int r = id >> 3, ck = id & 7;
            uint32_t soff = (uint32_t)(r * 128 + SWZ128(ck, r));
            size_t go = (size_t)r * ldb + kb + (size_t)ck * 16;
            cp16(sb +         soff, pAh + go);
            cp16(sb + 16384 + soff, pAl + go);
            cp16(sb + 32768 + soff, pBh + go);
            cp16(sb + 49152 + soff, pBl + go);
        }
        cp_commit();
    }

    float acc[4][4][4] = {};

    for (int s = 0; s < NS; s++) {
        if (s == NS - 1) cp_wait<0>(); else cp_wait<1>();
        __syncthreads();
        if (s + 2 < NS) {
            uint32_t sb = sbase + (uint32_t)(((s + 2) % 3) * 65536);
            size_t kb = (size_t)(s + 2) * 128;
            #pragma unroll
            for (int i = 0; i < 4; i++) {
                int id = tid + 256 * i;
                int r = id >> 3, ck = id & 7;
                uint32_t soff = (uint32_t)(r * 128 + SWZ128(ck, r));
                size_t go = (size_t)r * ldb + kb + (size_t)ck * 16;
                cp16(sb +         soff, pAh + go);
                cp16(sb + 16384 + soff, pAl + go);
                cp16(sb + 32768 + soff, pBh + go);
                cp16(sb + 49152 + soff, pBl + go);
            }
            cp_commit();
        }
        uint32_t base = sbase + (uint32_t)((s % 3) * 65536);
        #pragma unroll
        for (int ks = 0; ks < 4; ks++) {
            uint32_t ah[4][4], al[4][4], bh[4][2], bl[4][2];
            #pragma unroll
            for (int mi = 0; mi < 4; mi++) {
                int r = wM * 64 + mi * 16 + (lane & 15);
                int chunk = ks * 2 + (lane >> 4);
                uint32_t ad = base + (uint32_t)(r * 128 + SWZ128(chunk, r));
                ldsm4(ah[mi], ad);
                ldsm4(al[mi], ad + 16384u);
            }
            #pragma unroll
            for (int np = 0; np < 2; np++) {
                int g = lane >> 3, rr = lane & 7;
                int nl = wN * 32 + np * 16 + ((g & 2) << 2) + rr;
                int chunk = ks * 2 + (g & 1);
                uint32_t bd = base + 32768u +
                    (uint32_t)(nl * 128 + SWZ128(chunk, nl));
                uint32_t t0[4], t1[4];
                ldsm4(t0, bd);
                ldsm4(t1, bd + 16384u);
                bh[np*2][0] = t0[0]; bh[np*2][1] = t0[1];
                bh[np*2+1][0] = t0[2]; bh[np*2+1][1] = t0[3];
                bl[np*2][0] = t1[0]; bl[np*2][1] = t1[1];
                bl[np*2+1][0] = t1[2]; bl[np*2+1][1] = t1[3];
            }
            // term-major ordering: no back-to-back same-accumulator MMAs
            #pragma unroll
            for (int mi = 0; mi < 4; mi++)
                #pragma unroll
                for (int nj = 0; nj < 4; nj++)
                    mma16816(acc[mi][nj], ah[mi], bh[nj]);
            #pragma unroll
            for (int mi = 0; mi < 4; mi++)
                #pragma unroll
                for (int nj = 0; nj < 4; nj++)
                    mma16816(acc[mi][nj], ah[mi], bl[nj]);
            #pragma unroll
            for (int mi = 0; mi < 4; mi++)
                #pragma unroll
                for (int nj = 0; nj < 4; nj++)
                    mma16816(acc[mi][nj], al[mi], bh[nj]);
        }
    }

    // ---------------- epilogue from register accumulators ----------------
    const int rb = m0 + wM * 64 + (lane >> 2);
    const int cb = n0 + wN * 32 + (lane & 3) * 2;
    #pragma unroll
    for (int mi = 0; mi < 4; mi++) {
        #pragma unroll
        for (int nj = 0; nj < 4; nj++) {
            int r0 = rb + mi * 16;
            int c = cb + nj * 8;
            float* a = acc[mi][nj];
            float b0 = 0.f, b1 = 0.f;
            if (EPI >= 1 && EPI <= 3) {
                float2 bv = *(const float2*)(bias + c);
                b0 = bv.x; b1 = bv.y;
            }
            float v0 = a[0] + b0, v1 = a[1] + b1;
            float v2 = a[2] + b0, v3 = a[3] + b1;
            if (EPI == 2) {
                v0 = fmaxf(v0, 0.f); v1 = fmaxf(v1, 0.f);
                v2 = fmaxf(v2, 0.f); v3 = fmaxf(v3, 0.f);
            }
            if (EPI == 2 || EPI == 4) {
                __nv_bfloat16 h0, l0, h1, l1;
                split2(v0, h0, l0); split2(v1, h1, l1);
                __nv_bfloat162 ph; ph.x = h0; ph.y = h1;
                __nv_bfloat162 pl; pl.x = l0; pl.y = l1;
                *(__nv_bfloat162*)(Chi + (size_t)r0 * N + c) = ph;
                *(__nv_bfloat162*)(Clo + (size_t)r0 * N + c) = pl;
                split2(v2, h0, l0); split2(v3, h1, l1);
                ph.x = h0; ph.y = h1; pl.x = l0; pl.y = l1;
                *(__nv_bfloat162*)(Chi + (size_t)(r0 + 8) * N + c) = ph;
                *(__nv_bfloat162*)(Clo + (size_t)(r0 + 8) * N + c) = pl;
            } else {
                if (EPI == 3) {
                    float2 r1 = *(const float2*)(res + (size_t)r0 * N + c);
                    float2 r2 = *(const float2*)(res + (size_t)(r0 + 8) * N + c);
                    v0 += r1.x; v1 += r1.y; v2 += r2.x; v3 += r2.y;
                }
                float2 o1 = {v0, v1}, o2 = {v2, v3};
                *(float2*)(C + (size_t)r0 * N + c) = o1;
                *(float2*)(C + (size_t)(r0 + 8) * N + c) = o2;
            }
        }
    }
}

// ====== tensor-core attention scores: S = scale * Q K^T, 128x128 tiles ======
__global__ void __launch_bounds__(256, 1) attn_scores_tc(
    const __nv_bfloat16* __restrict__ Qhi, const __nv_bfloat16* __restrict__ Qlo,
    const __nv_bfloat16* __restrict__ Khi, const __nv_bfloat16* __restrict__ Klo,
    float* __restrict__ S)
{
    int bj = blockIdx.x, bi = blockIdx.y;
    if (bj > bi) return;
    int batch = blockIdx.z;
    int b = batch >> 4, h = batch & 15;

    extern __shared__ char dsm[];
    uint32_t sbase = smem_u32(dsm);
    sbase = (sbase + 1023u) & ~1023u;

    const int tid = threadIdx.x;
    const int lane = tid & 31;
    const int wM = (tid >> 5) >> 2;
    const int wN = (tid >> 5) & 3;

    const size_t lda = (size_t)Dn * 2;
    const char* pQh = (const char*)(Qhi + ((size_t)(b * Tn + bi * 128)) * Dn + h * 64);
    const char* pQl = (const char*)(Qlo + ((size_t)(b * Tn + bi * 128)) * Dn + h * 64);
    const char* pKh = (const char*)(Khi + ((size_t)(b * Tn + bj * 128)) * Dn + h * 64);
    const char* pKl = (const char*)(Klo + ((size_t)(b * Tn + bj * 128)) * Dn + h * 64);

    #pragma unroll
    for (int i = 0; i < 4; i++) {
        int id = tid + 256 * i;
        int r = id >> 3, ck = id & 7;
        uint32_t soff = (uint32_t)(r * 128 + SWZ128(ck, r));
        size_t go = (size_t)r * lda + (size_t)ck * 16;
        cp16(sbase +         soff, pQh + go);
        cp16(sbase + 16384 + soff, pQl + go);
        cp16(sbase + 32768 + soff, pKh + go);
        cp16(sbase + 49152 + soff, pKl + go);
    }
    cp_commit();
    cp_wait<0>();
    __syncthreads();

    float acc[4][4][4] = {};
    #pragma unroll
    for (int ks = 0; ks < 4; ks++) {
        uint32_t ah[4][4], al[4][4], bh[4][2], bl[4][2];
        #pragma unroll
        for (int mi = 0; mi < 4; mi++) {
            int r = wM * 64 + mi * 16 + (lane & 15);
            int chunk = ks * 2 + (lane >> 4);
            uint32_t ad = sbase + (uint32_t)(r * 128 + SWZ128(chunk, r));
            ldsm4(ah[mi], ad);
            ldsm4(al[mi], ad + 16384u);
        }
        #pragma unroll
        for (int np = 0; np < 2; np++) {
            int g = lane >> 3, rr = lane & 7;
            int nl = wN * 32 + np * 16 + ((g & 2) << 2) + rr;
            int chunk = ks * 2 + (g & 1);
            uint32_t bd = sbase + 32768u + (uint32_t)(nl * 128 + SWZ128(chunk, nl));
            uint32_t t0[4], t1[4];
            ldsm4(t0, bd);
            ldsm4(t1, bd + 16384u);
            bh[np*2][0] = t0[0]; bh[np*2][1] = t0[1];
            bh[np*2+1][0] = t0[2]; bh[np*2+1][1] = t0[3];
            bl[np*2][0] = t1[0]; bl[np*2][1] = t1[1];
            bl[np*2+1][0] = t1[2]; bl[np*2+1][1] = t1[3];
        }
        #pragma unroll
        for (int mi = 0; mi < 4; mi++)
            #pragma unroll
            for (int nj = 0; nj < 4; nj++)
                mma16816(acc[mi][nj], ah[mi], bh[nj]);
        #pragma unroll
        for (int mi = 0; mi < 4; mi++)
            #pragma unroll
            for (int nj = 0; nj < 4; nj++)
                mma16816(acc[mi][nj], ah[mi], bl[nj]);
        #pragma unroll
        for (int mi = 0; mi < 4; mi++)
            #pragma unroll
            for (int nj = 0; nj < 4; nj++)
                mma16816(acc[mi][nj], al[mi], bh[nj]);
    }

    const float scale = 0.125f;   // 1/sqrt(64)
    const int rb = bi * 128 + wM * 64 + (lane >> 2);
    const int cb = bj * 128 + wN * 32 + (lane & 3) * 2;
    float* Sb = S + (size_t)batch * Tn * Tn;
    #pragma unroll
    for (int mi = 0; mi < 4; mi++) {
        #pragma unroll
        for (int nj = 0; nj < 4; nj++) {
            int r0 = rb + mi * 16;
            int c = cb + nj * 8;
            float* a = acc[mi][nj];
            float2 o1 = {a[0] * scale, a[1] * scale};
            float2 o2 = {a[2] * scale, a[3] * scale};
            *(float2*)(Sb + (size_t)r0 * Tn + c) = o1;
            *(float2*)(Sb + (size_t)(r0 + 8) * Tn + c) = o2;
        }
    }
}

// ---------------- causal softmax: fp32 S -> bf16 hi/lo P ----------------
__global__ void softmax_kernel(float* __restrict__ S,
                               __nv_bfloat16* __restrict__ Phi,
                               __nv_bfloat16* __restrict__ Plo) {
    __shared__ float red[8];
    __shared__ float bcast;
    size_t r = blockIdx.x;
    int i = (int)(r & (Tn - 1));
    float* row = S + r * (size_t)Tn;
    int tid = threadIdx.x, lane = tid & 31, warp = tid >> 5;

    float m = -3.4e38f;
    for (int j = tid; j <= i; j += 256) m = fmaxf(m, row[j]);
    #pragma unroll
    for (int o = 16; o; o >>= 1) m = fmaxf(m, __shfl_xor_sync(0xffffffffu, m, o));
    if (!lane) red[warp] = m;
    __syncthreads();
    if (tid < 32) {
        float t = (lane < 8) ? red[lane] : -3.4e38f;
        #pragma unroll
        for (int o = 4; o; o >>= 1) t = fmaxf(t, __shfl_xor_sync(0xffffffffu, t, o));
        if (!lane) bcast = t;
    }
    __syncthreads();
    m = bcast;

    float sum = 0.f;
    for (int j = tid; j <= i; j += 256) {
        float e = __expf(row[j] - m);
        row[j] = e;
        sum += e;
    }
    #pragma unroll
    for (int o = 16; o; o >>= 1) sum += __shfl_xor_sync(0xffffffffu, sum, o);
    __syncthreads();
    if (!lane) red[warp] = sum;
    __syncthreads();
    if (tid < 32) {
        float t = (lane < 8) ? red[lane] : 0.f;
        #pragma unroll
        for (int o = 4; o; o >>= 1) t += __shfl_xor_sync(0xffffffffu, t, o);
        if (!lane) bcast = t;
    }
    __syncthreads();
    float inv = 1.f / bcast;
    int jend = ((i >> 7) + 1) << 7;       // AV reads 128-tiles jt <= i>>7
    __nv_bfloat16* ph = Phi + r * (size_t)Tn;
    __nv_bfloat16* pl = Plo + r * (size_t)Tn;
    for (int j = tid; j < jend; j += 256) {
        float val = (j <= i) ? row[j] * inv : 0.f;
        __nv_bfloat16 hb, lb;
        split2(val, hb, lb);
        ph[j] = hb; pl[j] = lb;
    }
}

// ====== tensor-core O = P @ V: 128x64 out per block, K-loop over jt =========
__global__ void __launch_bounds__(256, 1) attn_av_tc(
    const __nv_bfloat16* __restrict__ Phi, const __nv_bfloat16* __restrict__ Plo,
    const __nv_bfloat16* __restrict__ Vhi, const __nv_bfloat16* __restrict__ Vlo,
    __nv_bfloat16* __restrict__ Ohi, __nv_bfloat16* __restrict__ Olo)
{
    int bi = blockIdx.x;
    int batch = blockIdx.y;
    int b = batch >> 4, h = batch & 15;

    extern __shared__ char dsm[];
    uint32_t sbase = smem_u32(dsm);
    sbase = (sbase + 1023u) & ~1023u;

    const int tid = threadIdx.x;
    const int lane = tid & 31;
    const int wM = (tid >> 5) >> 2;     // 0..1 (64 rows each)
    const int wN = (tid >> 5) & 3;      // 0..3 (16 cols each)

    const size_t ldp = (size_t)Tn * 2;
    const size_t ldv = (size_t)Dn * 2;
    const char* pPh = (const char*)(Phi + ((size_t)batch * Tn + bi * 128) * Tn);
    const char* pPl = (const char*)(Plo + ((size_t)batch * Tn + bi * 128) * Tn);
    const char* pVh = (const char*)(Vhi + (size_t)(b * Tn) * Dn + h * 64);
    const char* pVl = (const char*)(Vlo + (size_t)(b * Tn) * Dn + h * 64);

    // stage layout: Ph 0, Pl 32768, Vh 65536, Vl 81920; stage stride 98304
    auto load_stage = [&](int jt, int stg) {
        uint32_t sb = sbase + (uint32_t)(stg * 98304);
        size_t pcol = (size_t)(jt * 128) * 2;
        #pragma unroll
        for (int i = 0; i < 8; i++) {
            int id = tid + 256 * i;
            int r = id >> 4, ck = id & 15;
            uint32_t soff = (uint32_t)(r * 256 + SWZ256(ck, r));
            size_t go = (size_t)r * ldp + pcol + (size_t)ck * 16;
            cp16(sb +         soff, pPh + go);
            cp16(sb + 32768 + soff, pPl + go);
        }
        #pragma unroll
        for (int i = 0; i < 4; i++) {
            int id = tid + 256 * i;
            int r = id >> 3, ck = id & 7;
            uint32_t soff = (uint32_t)(r * 128 + SWZ128(ck, r));
            size_t go = (size_t)(jt * 128 + r) * ldv + (size_t)ck * 16;
            cp16(sb + 65536 + soff, pVh + go);
            cp16(sb + 81920 + soff, pVl + go);
        }
        cp_commit();
    };

    load_stage(0, 0);
    float acc[4][2][4] = {};

    for (int jt = 0; jt <= bi; jt++) {
        cp_wait<0>();
        __syncthreads();
        if (jt < bi) load_stage(jt + 1, (jt + 1) & 1);
        uint32_t base = sbase + (uint32_t)((jt & 1) * 98304);
        #pragma unroll
        for (int ks = 0; ks < 8; ks++) {
            uint32_t ah[4][4], al[4][4], bh[2][2], bl[2][2];
            #pragma unroll
            for (int mi = 0; mi < 4; mi++) {
                int r = wM * 64 + mi * 16 + (lane & 15);
                int chunk = ks * 2 + (lane >> 4);
                uint32_t ad = base + (uint32_t)(r * 256 + SWZ256(chunk, r));
                ldsm4(ah[mi], ad);
                ldsm4(al[mi], ad + 32768u);
            }
            {
                int g = lane >> 3;
                int row = ks * 16 + ((g & 1) << 3) + (lane & 7);
                int chunk = wN * 2 + (g >> 1);
                uint32_t bd = base + 65536u +
                    (uint32_t)(row * 128 + SWZ128(chunk, row));
                uint32_t t0[4], t1[4];
                ldsm4t(t0, bd);
                ldsm4t(t1, bd + 16384u);
                bh[0][0] = t0[0]; bh[0][1] = t0[1];
                bh[1][0] = t0[2]; bh[1][1] = t0[3];
                bl[0][0] = t1[0]; bl[0][1] = t1[1];
                bl[1][0] = t1[2]; bl[1][1] = t1[3];
            }
            #pragma unroll
            for (int mi = 0; mi < 4; mi++)
                #pragma unroll
                for (int nj = 0; nj < 2; nj++)
                    mma16816(acc[mi][nj], ah[mi], bh[nj]);
            #pragma unroll
            for (int mi = 0; mi < 4; mi++)
                #pragma unroll
                for (int nj = 0; nj < 2; nj++)
                    mma16816(acc[mi][nj], ah[mi], bl[nj]);
            #pragma unroll
            for (int mi = 0; mi < 4; mi++)
                #pragma unroll
                for (int nj = 0; nj < 2; nj++)
                    mma16816(acc[mi][nj], al[mi], bh[nj]);
        }
        __syncthreads();
    }

    const int rb = bi * 128 + wM * 64 + (lane >> 2);
    const int cb = wN * 16 + (lane & 3) * 2;
    #pragma unroll
    for (int mi = 0; mi < 4; mi++) {
        #pragma unroll
        for (int nj = 0; nj < 2; nj++) {
            int r0 = rb + mi * 16;
            int c = cb + nj * 8;
            float* a = acc[mi][nj];
            size_t off0 = ((size_t)(b * Tn) + r0) * Dn + h * 64 + c;
            size_t off1 = ((size_t)(b * Tn) + r0 + 8) * Dn + h * 64 + c;
            __nv_bfloat16 h0, l0, h1, l1;
            split2(a[0], h0, l0); split2(a[1], h1, l1);
            __nv_bfloat162 ph; ph.x = h0; ph.y = h1;
            __nv_bfloat162 pl; pl.x = l0; pl.y = l1;
            *(__nv_bfloat162*)(Ohi + off0) = ph;
            *(__nv_bfloat162*)(Olo + off0) = pl;
            split2(a[2], h0, l0); split2(a[3], h1, l1);
            ph.x = h0; ph.y = h1; pl.x = l0; pl.y = l1;
            *(__nv_bfloat162*)(Ohi + off1) = ph;
            *(__nv_bfloat162*)(Olo + off1) = pl;
        }
    }
}

// ---------------- launch ----------------
#define SMEM_GEMM (1024 + 3 * 65536)
#define SMEM_SC   (1024 + 65536)
#define SMEM_AV   (1024 + 2 * 98304)

extern "C" void kernel_launch(void* const* d_in, const int* in_sizes, int n_in,
                              void* d_out, int out_size) {
    const int*   ctx  = (const int*)  d_in[0];
    const float* tok  = (const float*)d_in[1];
    const float* pos  = (const float*)d_in[2];
    const float* Wq   = (const float*)d_in[3];
    const float* Wk   = (const float*)d_in[4];
    const float* Wv   = (const float*)d_in[5];
    const float* Wo   = (const float*)d_in[6];
    const float* bo   = (const float*)d_in[7];
    const float* ln1s = (const float*)d_in[8];
    const float* ln1b = (const float*)d_in[9];
    const float* W1   = (const float*)d_in[10];
    const float* b1   = (const float*)d_in[11];
    const float* W2   = (const float*)d_in[12];
    const float* b2   = (const float*)d_in[13];
    const float* ln2s = (const float*)d_in[14];
    const float* ln2b = (const float*)d_in[15];
    const float* lnfs = (const float*)d_in[16];
    const float* lnfb = (const float*)d_in[17];
    const float* Wout = (const float*)d_in[18];
    const float* bout = (const float*)d_in[19];
    float* out = (float*)d_out;

    float *x, *S;
    __nv_bfloat16 *hhi, *hlo, *qhi, *qlo, *khi, *klo, *vhi, *vlo;
    __nv_bfloat16 *ohi, *olo, *fhi, *flo, *phi, *plo;
    __nv_bfloat16 *wqh, *wql, *wkh, *wkl, *wvh, *wvl, *woh, *wol;
    __nv_bfloat16 *w1h, *w1l, *w2h, *w2l, *wouth, *woutl;
    cudaGetSymbolAddress((void**)&x, g_x);
    cudaGetSymbolAddress((void**)&S, g_S);
    cudaGetSymbolAddress((void**)&phi, g_phi);
    cudaGetSymbolAddress((void**)&plo, g_plo);
    cudaGetSymbolAddress((void**)&hhi, g_hhi);
    cudaGetSymbolAddress((void**)&hlo, g_hlo);
    cudaGetSymbolAddress((void**)&qhi, g_qhi);
    cudaGetSymbolAddress((void**)&qlo, g_qlo);
    cudaGetSymbolAddress((void**)&khi, g_khi);
    cudaGetSymbolAddress((void**)&klo, g_klo);
    cudaGetSymbolAddress((void**)&vhi, g_vhi);
    cudaGetSymbolAddress((void**)&vlo, g_vlo);
    cudaGetSymbolAddress((void**)&ohi, g_ohi);
    cudaGetSymbolAddress((void**)&olo, g_olo);
    cudaGetSymbolAddress((void**)&fhi, g_fhi);
    cudaGetSymbolAddress((void**)&flo, g_flo);
    cudaGetSymbolAddress((void**)&wqh, g_wqt_hi);
    cudaGetSymbolAddress((void**)&wql, g_wqt_lo);
    cudaGetSymbolAddress((void**)&wkh, g_wkt_hi);
    cudaGetSymbolAddress((void**)&wkl, g_wkt_lo);
    cudaGetSymbolAddress((void**)&wvh, g_wvt_hi);
    cudaGetSymbolAddress((void**)&wvl, g_wvt_lo);
    cudaGetSymbolAddress((void**)&woh, g_wot_hi);
    cudaGetSymbolAddress((void**)&wol, g_wot_lo);
    cudaGetSymbolAddress((void**)&w1h, g_w1t_hi);
    cudaGetSymbolAddress((void**)&w1l, g_w1t_lo);
    cudaGetSymbolAddress((void**)&w2h, g_w2t_hi);
    cudaGetSymbolAddress((void**)&w2l, g_w2t_lo);
    cudaGetSymbolAddress((void**)&wouth, g_woutt_hi);
    cudaGetSymbolAddress((void**)&woutl, g_woutt_lo);

    cudaFuncSetAttribute(mmagemm<1>, cudaFuncAttributeMaxDynamicSharedMemorySize, SMEM_GEMM);
    cudaFuncSetAttribute(mmagemm<2>, cudaFuncAttributeMaxDynamicSharedMemorySize, SMEM_GEMM);
    cudaFuncSetAttribute(mmagemm<3>, cudaFuncAttributeMaxDynamicSharedMemorySize, SMEM_GEMM);
    cudaFuncSetAttribute(mmagemm<4>, cudaFuncAttributeMaxDynamicSharedMemorySize, SMEM_GEMM);
    cudaFuncSetAttribute(attn_scores_tc, cudaFuncAttributeMaxDynamicSharedMemorySize, SMEM_SC);
    cudaFuncSetAttribute(attn_av_tc, cudaFuncAttributeMaxDynamicSharedMemorySize, SMEM_AV);

    // weight prep (runs inside the graph; deterministic)
    {
        dim3 blk(32, 8);
        dim3 gDD(Dn / 32, Dn / 32);
        dim3 gDF(Fn / 32, Dn / 32);
        dim3 gFD(Dn / 32, Fn / 32);
        dim3 gDV(Vn / 32, Dn / 32);
        for (int l = 0; l < NLAYER; l++) {
            size_t dd = (size_t)l * Dn * Dn;
            size_t df = (size_t)l * Dn * Fn;
            wconv_kernel<<<gDD, blk>>>(Wq + dd, wqh + dd, wql + dd, Dn, Dn);
            wconv_kernel<<<gDD, blk>>>(Wk + dd, wkh + dd, wkl + dd, Dn, Dn);
            wconv_kernel<<<gDD, blk>>>(Wv + dd, wvh + dd, wvl + dd, Dn, Dn);
            wconv_kernel<<<gDD, blk>>>(Wo + dd, woh + dd, wol + dd, Dn, Dn);
            wconv_kernel<<<gDF, blk>>>(W1 + df, w1h + df, w1l + df, Dn, Fn);
            wconv_kernel<<<gFD, blk>>>(W2 + df, w2h + df, w2l + df, Fn, Dn);
        }
        wconv_kernel<<<gDV, blk>>>(Wout, wouth, woutl, Dn, Vn);
    }

    embed_kernel<<<NROWS, 256>>>(ctx, tok, pos, x);

    dim3 gD(Dn / 128, NROWS / 128);     // (8, 32)
    dim3 gF(Fn / 128, NROWS / 128);     // (32, 32)
    dim3 gV(Vn / 128, NROWS / 128);     // (250, 32)
    dim3 gScore(Tn / 128, Tn / 128, Bn * Hn);
    dim3 gAV(Tn / 128, Bn * Hn);

    for (int l = 0; l < NLAYER; l++) {
        size_t dd = (size_t)l * Dn * Dn;
        size_t df = (size_t)l * Dn * Fn;

        ln_kernel<<<NROWS, 256>>>(x, ln1s + l * Dn, ln1b + l * Dn, hhi, hlo);
        mmagemm<4><<<gD, 256, SMEM_GEMM>>>(hhi, hlo, wqh + dd, wql + dd,
                                           nullptr, nullptr, nullptr, qhi, qlo, Dn, Dn);
        mmagemm<4><<<gD, 256, SMEM_GEMM>>>(hhi, hlo, wkh + dd, wkl + dd,
                                           nullptr, nullptr, nullptr, khi, klo, Dn, Dn);
        mmagemm<4><<<gD, 256, SMEM_GEMM>>>(hhi, hlo, wvh + dd, wvl + dd,
                                           nullptr, nullptr, nullptr, vhi, vlo, Dn, Dn);

        attn_scores_tc<<<gScore, 256, SMEM_SC>>>(qhi, qlo, khi, klo, S);
        softmax_kernel<<<Bn * Hn * Tn, 256>>>(S, phi, plo);
        attn_av_tc<<<gAV, 256, SMEM_AV>>>(phi, plo, vhi, vlo, ohi, olo);

        // x = x + o @ Wo + bo
        mmagemm<3><<<gD, 256, SMEM_GEMM>>>(ohi, olo, woh + dd, wol + dd,
                                           bo + l * Dn, x, x, nullptr, nullptr, Dn, Dn);

        ln_kernel<<<NROWS, 256>>>(x, ln2s + l * Dn, ln2b + l * Dn, hhi, hlo);
        // f = relu(h @ W1 + b1) -> bf16 hi/lo
        mmagemm<2><<<gF, 256, SMEM_GEMM>>>(hhi, hlo, w1h + df, w1l + df,
                                           b1 + l * Fn, nullptr, nullptr, fhi, flo, Fn, Dn);
        // x = x + f @ W2 + b2
        mmagemm<3><<<gD, 256, SMEM_GEMM>>>(fhi, flo, w2h + df, w2l + df,
                                           b2 + l * Dn, x, x, nullptr, nullptr, Dn, Fn);
    }

    ln_kernel<<<NROWS, 256>>>(x, lnfs, lnfb, hhi, hlo);
    mmagemm<1><<<gV, 256, SMEM_GEMM>>>(hhi, hlo, wouth, woutl,
                                       bout, nullptr, out, nullptr, nullptr, Vn, Dn);
}

// round 13
// speedup vs baseline: 4.0916x; 1.3409x over previous
#include <cuda_runtime.h>
#include <cuda_fp16.h>
#include <math.h>
#include <stdint.h>

#define Tn 2048
#define Dn 1024
#define Hn 16
#define Bn 2
#define Vn 32000
#define Fn 4096
#define NLAYER 4
#define NROWS (Bn*Tn)   // 4096
#define KCH 64          // K chunk per pipeline stage = 128 bytes/row fp16

// ---------------- scratch (static device allocations only) ----------------
__device__ float g_x[(size_t)NROWS*Dn];
__device__ float g_S[(size_t)Bn*Hn*Tn*Tn];      // fp32 scores
__device__ __half g_phi[(size_t)Bn*Hn*Tn*Tn];   // probs (single fp16)

__device__ __half g_hhi[(size_t)NROWS*Dn];
__device__ __half g_hlo[(size_t)NROWS*Dn];
__device__ __half g_qhi[(size_t)NROWS*Dn];
__device__ __half g_qlo[(size_t)NROWS*Dn];
__device__ __half g_khi[(size_t)NROWS*Dn];      // K single
__device__ __half g_vhi[(size_t)NROWS*Dn];
__device__ __half g_vlo[(size_t)NROWS*Dn];
__device__ __half g_ohi[(size_t)NROWS*Dn];
__device__ __half g_olo[(size_t)NROWS*Dn];
__device__ __half g_fhi[(size_t)NROWS*Fn];
__device__ __half g_flo[(size_t)NROWS*Fn];

// transposed weights: [N, K] K-major, single fp16
__device__ __half g_wqt[(size_t)NLAYER*Dn*Dn];
__device__ __half g_wkt[(size_t)NLAYER*Dn*Dn];
__device__ __half g_wvt[(size_t)NLAYER*Dn*Dn];
__device__ __half g_wot[(size_t)NLAYER*Dn*Dn];
__device__ __half g_w1t[(size_t)NLAYER*Dn*Fn];
__device__ __half g_w2t[(size_t)NLAYER*Fn*Dn];
__device__ __half g_woutt[(size_t)Vn*Dn];

// ---------------- PTX helpers (baseline sm_80-class only) ----------------
__device__ __forceinline__ uint32_t smem_u32(const void* p) {
    uint32_t a;
    asm("{ .reg .u64 t; cvta.to.shared.u64 t, %1; cvt.u32.u64 %0, t; }"
        : "=r"(a) : "l"(p));
    return a;
}
__device__ __forceinline__ void cp16(uint32_t s, const void* g) {
    asm volatile("cp.async.cg.shared.global [%0], [%1], 16;"
                 :: "r"(s), "l"(g));
}
__device__ __forceinline__ void cp_commit() {
    asm volatile("cp.async.commit_group;" ::: "memory");
}
template <int Ng> __device__ __forceinline__ void cp_wait() {
    asm volatile("cp.async.wait_group %0;" :: "n"(Ng) : "memory");
}
__device__ __forceinline__ void ldsm4(uint32_t* r, uint32_t addr) {
    asm volatile("ldmatrix.sync.aligned.m8n8.x4.shared.b16 {%0,%1,%2,%3}, [%4];"
                 : "=r"(r[0]), "=r"(r[1]), "=r"(r[2]), "=r"(r[3]) : "r"(addr));
}
__device__ __forceinline__ void ldsm4t(uint32_t* r, uint32_t addr) {
    asm volatile("ldmatrix.sync.aligned.m8n8.x4.trans.shared.b16 {%0,%1,%2,%3}, [%4];"
                 : "=r"(r[0]), "=r"(r[1]), "=r"(r[2]), "=r"(r[3]) : "r"(addr));
}
__device__ __forceinline__ void mma16816(float* c, const uint32_t* a,
                                         const uint32_t* b) {
    asm volatile(
        "mma.sync.aligned.m16n8k16.row.col.f32.f16.f16.f32 "
        "{%0,%1,%2,%3}, {%4,%5,%6,%7}, {%8,%9}, {%0,%1,%2,%3};"
        : "+f"(c[0]), "+f"(c[1]), "+f"(c[2]), "+f"(c[3])
        : "r"(a[0]), "r"(a[1]), "r"(a[2]), "r"(a[3]), "r"(b[0]), "r"(b[1]));
}
__device__ __forceinline__ void split2(float v, __half& h, __half& l) {
    h = __float2half(v);
    l = __float2half(v - __half2float(h));
}
// swizzles: 128B rows (8 x 16B chunks) and 256B rows (16 chunks)
#define SWZ128(c, r) (((c) ^ ((r) & 7)) << 4)
#define SWZ256(c, r) (((((c) ^ ((r) & 7)) & 7) | ((c) & 8)) << 4)

// ---------------- embedding ----------------
__global__ void embed_kernel(const int* __restrict__ ctx,
                             const float* __restrict__ tok,
                             const float* __restrict__ pos,
                             float* __restrict__ x) {
    int row = blockIdx.x;
    int t   = row & (Tn - 1);
    int id  = ctx[row];
    const float4* tp = (const float4*)(tok + (size_t)id * Dn);
    const float4* pp = (const float4*)(pos + (size_t)t * Dn);
    float4* xp = (float4*)(x + (size_t)row * Dn);
    int i = threadIdx.x;
    float4 a = tp[i], b = pp[i];
    a.x += b.x; a.y += b.y; a.z += b.z; a.w += b.w;
    xp[i] = a;
}

// ------------- weight transpose + fp16 round: W[K,N] -> Wt[N,K] -------------
__global__ void wconv_kernel(const float* __restrict__ W,
                             __half* __restrict__ hi,
                             int K, int N) {
    __shared__ float t[32][33];
    int tx = threadIdx.x, ty = threadIdx.y;
    int n = blockIdx.x * 32 + tx;
    int k0 = blockIdx.y * 32;
    #pragma unroll
    for (int j = 0; j < 4; j++)
        t[ty + 8 * j][tx] = W[(size_t)(k0 + ty + 8 * j) * N + n];
    __syncthreads();
    int nn0 = blockIdx.x * 32;
    #pragma unroll
    for (int j = 0; j < 4; j++) {
        int nn = nn0 + ty + 8 * j;
        int kk = k0 + tx;
        hi[(size_t)nn * K + kk] = __float2half(t[tx][ty + 8 * j]);
    }
}

// ---------------- layernorm -> fp16 hi/lo ----------------
__global__ void ln_kernel(const float* __restrict__ x,
                          const float* __restrict__ gam,
                          const float* __restrict__ bet,
                          __half* __restrict__ hhi,
                          __half* __restrict__ hlo) {
    __shared__ float ss[8], sq[8];
    int row = blockIdx.x;
    const float* xr = x + (size_t)row * Dn;
    int tid = threadIdx.x, lane = tid & 31, warp = tid >> 5;
    float v[4]; float s = 0.f, q = 0.f;
    #pragma unroll
    for (int i = 0; i < 4; i++) {
        v[i] = xr[tid + 256 * i];
        s += v[i]; q += v[i] * v[i];
    }
    #pragma unroll
    for (int o = 16; o; o >>= 1) {
        s += __shfl_xor_sync(0xffffffffu, s, o);
        q += __shfl_xor_sync(0xffffffffu, q, o);
    }
    if (!lane) { ss[warp] = s; sq[warp] = q; }
    __syncthreads();
    if (tid < 32) {
        float ts = (lane < 8) ? ss[lane] : 0.f;
        float tq = (lane < 8) ? sq[lane] : 0.f;
        #pragma unroll
        for (int o = 4; o; o >>= 1) {
            ts += __shfl_xor_sync(0xffffffffu, ts, o);
            tq += __shfl_xor_sync(0xffffffffu, tq, o);
        }
        if (!lane) { ss[0] = ts; sq[0] = tq; }
    }
    __syncthreads();
    float mean = ss[0] * (1.f / Dn);
    float var  = sq[0] * (1.f / Dn) - mean * mean;
    float r = rsqrtf(var + 1e-5f);
    #pragma unroll
    for (int i = 0; i < 4; i++) {
        int c = tid + 256 * i;
        float y = (v[i] - mean) * r * gam[c] + bet[c];
        __half h, l;
        split2(y, h, l);
        hhi[(size_t)row * Dn + c] = h;
        hlo[(size_t)row * Dn + c] = l;
    }
}

// ====== mma.sync fp16 2-term GEMM: C = (Ah+Al)[M,K] @ B[N,K]^T ==============
// EPI: 1 = +bias (fp32), 2 = +bias,relu -> fp16 hi/lo,
//      3 = +bias,+res (fp32), 4 = plain -> fp16 hi/lo, 5 = plain -> fp16 single
template <int EPI>
__global__ void __launch_bounds__(256, 1) mmagemm(
    const __half* __restrict__ Ahi, const __half* __restrict__ Alo,
    const __half* __restrict__ Bt,
    const float* __restrict__ bias, const float* __restrict__ res,
    float* __restrict__ C,
    __half* __restrict__ Chi, __half* __restrict__ Clo,
    int N, int Kt)
{
    extern __shared__ char dsm[];
    const int tid = threadIdx.x;
    const int lane = tid & 31;
    const int wM = (tid >> 5) >> 2;     // 0..1
    const int wN = (tid >> 5) & 3;      // 0..3
    const int m0 = blockIdx.y * 128;
    const int n0 = blockIdx.x * 128;

    uint32_t sbase = smem_u32(dsm);
    sbase = (sbase + 1023u) & ~1023u;

    const char* pAh = (const char*)(Ahi + (size_t)m0 * Kt);
    const char* pAl = (const char*)(Alo + (size_t)m0 * Kt);
    const char* pB  = (const char*)(Bt  + (size_t)n0 * Kt);
    const size_t ldb = (size_t)Kt * 2;
    const int NS = Kt / KCH;
    const uint32_t SST = 49152u;        // stage stride: Ah 16K | Al 16K | B 16K

    #pragma unroll
    for (int ps = 0; ps < 2; ps++) {
        uint32_t sb = sbase + (uint32_t)ps * SST;
        size_t kb = (size_t)ps * 128;
        #pragma unroll
        for (int i = 0; i < 4; i++) {
            int id = tid + 256 * i;
            int r = id >> 3, ck = id & 7;
            uint32_t soff = (uint32_t)(r * 128 + SWZ128(ck, r));
            size_t go = (size_t)r * ldb + kb + (size_t)ck * 16;
            cp16(sb +         soff, pAh + go);
            cp16(sb + 16384 + soff, pAl + go);
            cp16(sb + 32768 + soff, pB + go);
        }
        cp_commit();
    }

    float acc[4][4][4] = {};

    for (int s = 0; s < NS; s++) {
        if (s == NS - 1) cp_wait<0>(); else cp_wait<1>();
        __syncthreads();
        if (s + 2 < NS) {
            uint32_t sb = sbase + (uint32_t)((s + 2) % 3) * SST;
            size_t kb = (size_t)(s + 2) * 128;
            #pragma unroll
            for (int i = 0; i < 4; i++) {
                int id = tid + 256 * i;
                int r = id >> 3, ck = id & 7;
                uint32_t soff = (uint32_t)(r * 128 + SWZ128(ck, r));
                size_t go = (size_t)r * ldb + kb + (size_t)ck * 16;
                cp16(sb +         soff, pAh + go);
                cp16(sb + 16384 + soff, pAl + go);
                cp16(sb + 32768 + soff, pB + go);
            }
            cp_commit();
        }
        uint32_t base = sbase + (uint32_t)(s % 3) * SST;
        #pragma unroll
        for (int ks = 0; ks < 4; ks++) {
            uint32_t ah[4][4], al[4][4], bq[4][2];
            #pragma unroll
            for (int mi = 0; mi < 4; mi++) {
                int r = wM * 64 + mi * 16 + (lane & 15);
                int chunk = ks * 2 + (lane >> 4);
                uint32_t ad = base + (uint32_t)(r * 128 + SWZ128(chunk, r));
                ldsm4(ah[mi], ad);
                ldsm4(al[mi], ad + 16384u);
            }
            #pragma unroll
            for (int np = 0; np < 2; np++) {
                int g = lane >> 3, rr = lane & 7;
                int nl = wN * 32 + np * 16 + ((g & 2) << 2) + rr;
                int chunk = ks * 2 + (g & 1);
                uint32_t bd = base + 32768u +
                    (uint32_t)(nl * 128 + SWZ128(chunk, nl));
                uint32_t t0[4];
                ldsm4(t0, bd);
                bq[np*2][0] = t0[0]; bq[np*2][1] = t0[1];
                bq[np*2+1][0] = t0[2]; bq[np*2+1][1] = t0[3];
            }
            #pragma unroll
            for (int mi = 0; mi < 4; mi++)
                #pragma unroll
                for (int nj = 0; nj < 4; nj++)
                    mma16816(acc[mi][nj], ah[mi], bq[nj]);
            #pragma unroll
            for (int mi = 0; mi < 4; mi++)
                #pragma unroll
                for (int nj = 0; nj < 4; nj++)
                    mma16816(acc[mi][nj], al[mi], bq[nj]);
        }
    }

    // ---------------- epilogue ----------------
    const int rb = m0 + wM * 64 + (lane >> 2);
    const int cb = n0 + wN * 32 + (lane & 3) * 2;
    #pragma unroll
    for (int mi = 0; mi < 4; mi++) {
        #pragma unroll
        for (int nj = 0; nj < 4; nj++) {
            int r0 = rb + mi * 16;
            int c = cb + nj * 8;
            float* a = acc[mi][nj];
            float b0 = 0.f, b1 = 0.f;
            if (EPI >= 1 && EPI <= 3) {
                float2 bv = *(const float2*)(bias + c);
                b0 = bv.x; b1 = bv.y;
            }
            float v0 = a[0] + b0, v1 = a[1] + b1;
            float v2 = a[2] + b0, v3 = a[3] + b1;
            if (EPI == 2) {
                v0 = fmaxf(v0, 0.f); v1 = fmaxf(v1, 0.f);
                v2 = fmaxf(v2, 0.f); v3 = fmaxf(v3, 0.f);
            }
            if (EPI == 2 || EPI == 4) {
                __half h0, l0, h1, l1;
                split2(v0, h0, l0); split2(v1, h1, l1);
                __half2 ph; ph.x = h0; ph.y = h1;
                __half2 pl; pl.x = l0; pl.y = l1;
                *(__half2*)(Chi + (size_t)r0 * N + c) = ph;
                *(__half2*)(Clo + (size_t)r0 * N + c) = pl;
                split2(v2, h0, l0); split2(v3, h1, l1);
                ph.x = h0; ph.y = h1; pl.x = l0; pl.y = l1;
                *(__half2*)(Chi + (size_t)(r0 + 8) * N + c) = ph;
                *(__half2*)(Clo + (size_t)(r0 + 8) * N + c) = pl;
            } else if (EPI == 5) {
                __half2 p1; p1.x = __float2half(v0); p1.y = __float2half(v1);
                __half2 p2; p2.x = __float2half(v2); p2.y = __float2half(v3);
                *(__half2*)(Chi + (size_t)r0 * N + c) = p1;
                *(__half2*)(Chi + (size_t)(r0 + 8) * N + c) = p2;
            } else {
                if (EPI == 3) {
                    float2 r1 = *(const float2*)(res + (size_t)r0 * N + c);
                    float2 r2 = *(const float2*)(res + (size_t)(r0 + 8) * N + c);
                    v0 += r1.x; v1 += r1.y; v2 += r2.x; v3 += r2.y;
                }
                float2 o1 = {v0, v1}, o2 = {v2, v3};
                *(float2*)(C + (size_t)r0 * N + c) = o1;
                *(float2*)(C + (size_t)(r0 + 8) * N + c) = o2;
            }
        }
    }
}

// ====== scores: S = scale * (Qh+Ql) K^T, 128x128 causal tiles ======
__global__ void __launch_bounds__(256, 1) attn_scores_tc(
    const __half* __restrict__ Qhi, const __half* __restrict__ Qlo,
    const __half* __restrict__ Kh,
    float* __restrict__ S)
{
    int bj = blockIdx.x, bi = blockIdx.y;
    if (bj > bi) return;
    int batch = blockIdx.z;
    int b = batch >> 4, h = batch & 15;

    extern __shared__ char dsm[];
    uint32_t sbase = smem_u32(dsm);
    sbase = (sbase + 1023u) & ~1023u;

    const int tid = threadIdx.x;
    const int lane = tid & 31;
    const int wM = (tid >> 5) >> 2;
    const int wN = (tid >> 5) & 3;

    const size_t lda = (size_t)Dn * 2;
    const char* pQh = (const char*)(Qhi + ((size_t)(b * Tn + bi * 128)) * Dn + h * 64);
    const char* pQl = (const char*)(Qlo + ((size_t)(b * Tn + bi * 128)) * Dn + h * 64);
    const char* pK  = (const char*)(Kh  + ((size_t)(b * Tn + bj * 128)) * Dn + h * 64);

    #pragma unroll
    for (int i = 0; i < 4; i++) {
        int id = tid + 256 * i;
        int r = id >> 3, ck = id & 7;
        uint32_t soff = (uint32_t)(r * 128 + SWZ128(ck, r));
        size_t go = (size_t)r * lda + (size_t)ck * 16;
        cp16(sbase +         soff, pQh + go);
        cp16(sbase + 16384 + soff, pQl + go);
        cp16(sbase + 32768 + soff, pK + go);
    }
    cp_commit();
    cp_wait<0>();
    __syncthreads();

    float acc[4][4][4] = {};
    #pragma unroll
    for (int ks = 0; ks < 4; ks++) {
        uint32_t ah[4][4], al[4][4], bq[4][2];
        #pragma unroll
        for (int mi = 0; mi < 4; mi++) {
            int r = wM * 64 + mi * 16 + (lane & 15);
            int chunk = ks * 2 + (lane >> 4);
            uint32_t ad = sbase + (uint32_t)(r * 128 + SWZ128(chunk, r));
            ldsm4(ah[mi], ad);
            ldsm4(al[mi], ad + 16384u);
        }
        #pragma unroll
        for (int np = 0; np < 2; np++) {
            int g = lane >> 3, rr = lane & 7;
            int nl = wN * 32 + np * 16 + ((g & 2) << 2) + rr;
            int chunk = ks * 2 + (g & 1);
            uint32_t bd = sbase + 32768u + (uint32_t)(nl * 128 + SWZ128(chunk, nl));
            uint32_t t0[4];
            ldsm4(t0, bd);
            bq[np*2][0] = t0[0]; bq[np*2][1] = t0[1];
            bq[np*2+1][0] = t0[2]; bq[np*2+1][1] = t0[3];
        }
        #pragma unroll
        for (int mi = 0; mi < 4; mi++)
            #pragma unroll
            for (int nj = 0; nj < 4; nj++)
                mma16816(acc[mi][nj], ah[mi], bq[nj]);
        #pragma unroll
        for (int mi = 0; mi < 4; mi++)
            #pragma unroll
            for (int nj = 0; nj < 4; nj++)
                mma16816(acc[mi][nj], al[mi], bq[nj]);
    }

    const float scale = 0.125f;
    const int rb = bi * 128 + wM * 64 + (lane >> 2);
    const int cb = bj * 128 + wN * 32 + (lane & 3) * 2;
    float* Sb = S + (size_t)batch * Tn * Tn;
    #pragma unroll
    for (int mi = 0; mi < 4; mi++) {
        #pragma unroll
        for (int nj = 0; nj < 4; nj++) {
            int r0 = rb + mi * 16;
            int c = cb + nj * 8;
            float* a = acc[mi][nj];
            float2 o1 = {a[0] * scale, a[1] * scale};
            float2 o2 = {a[2] * scale, a[3] * scale};
            *(float2*)(Sb + (size_t)r0 * Tn + c) = o1;
            *(float2*)(Sb + (size_t)(r0 + 8) * Tn + c) = o2;
        }
    }
}

// ---------------- causal softmax: fp32 S -> single fp16 P ----------------
__global__ void softmax_kernel(float* __restrict__ S,
                               __half* __restrict__ Phi) {
    __shared__ float red[8];
    __shared__ float bcast;
    size_t r = blockIdx.x;
    int i = (int)(r & (Tn - 1));
    float* row = S + r * (size_t)Tn;
    int tid = threadIdx.x, lane = tid & 31, warp = tid >> 5;

    float m = -3.4e38f;
    for (int j = tid; j <= i; j += 256) m = fmaxf(m, row[j]);
    #pragma unroll
    for (int o = 16; o; o >>= 1) m = fmaxf(m, __shfl_xor_sync(0xffffffffu, m, o));
    if (!lane) red[warp] = m;
    __syncthreads();
    if (tid < 32) {
        float t = (lane < 8) ? red[lane] : -3.4e38f;
        #pragma unroll
        for (int o = 4; o; o >>= 1) t = fmaxf(t, __shfl_xor_sync(0xffffffffu, t, o));
        if (!lane) bcast = t;
    }
    __syncthreads();
    m = bcast;

    float sum = 0.f;
    for (int j = tid; j <= i; j += 256) {
        float e = __expf(row[j] - m);
        row[j] = e;
        sum += e;
    }
    #pragma unroll
    for (int o = 16; o; o >>= 1) sum += __shfl_xor_sync(0xffffffffu, sum, o);
    __syncthreads();
    if (!lane) red[warp] = sum;
    __syncthreads();
    if (tid < 32) {
        float t = (lane < 8) ? red[lane] : 0.f;
        #pragma unroll
        for (int o = 4; o; o >>= 1) t += __shfl_xor_sync(0xffffffffu, t, o);
        if (!lane) bcast = t;
    }
    __syncthreads();
    float inv = 1.f / bcast;
    int jend = ((i >> 7) + 1) << 7;       // AV reads 128-tiles jt <= i>>7
    __half* ph = Phi + r * (size_t)Tn;
    for (int j = tid; j < jend; j += 256) {
        float val = (j <= i) ? row[j] * inv : 0.f;
        ph[j] = __float2half(val);
    }
}

// ====== O = P @ (Vh+Vl): 128x64 out per block, K-loop over jt ==============
__global__ void __launch_bounds__(256, 1) attn_av_tc(
    const __half* __restrict__ Phi,
    const __half* __restrict__ Vhi, const __half* __restrict__ Vlo,
    __half* __restrict__ Ohi, __half* __restrict__ Olo)
{
    int bi = blockIdx.x;
    int batch = blockIdx.y;
    int b = batch >> 4, h = batch & 15;

    extern __shared__ char dsm[];
    uint32_t sbase = smem_u32(dsm);
    sbase = (sbase + 1023u) & ~1023u;

    const int tid = threadIdx.x;
    const int lane = tid & 31;
    const int wM = (tid >> 5) >> 2;     // 0..1 (64 rows each)
    const int wN = (tid >> 5) & 3;      // 0..3 (16 cols each)

    const size_t ldp = (size_t)Tn * 2;
    const size_t ldv = (size_t)Dn * 2;
    const char* pP  = (const char*)(Phi + ((size_t)batch * Tn + bi * 128) * Tn);
    const char* pVh = (const char*)(Vhi + (size_t)(b * Tn) * Dn + h * 64);
    const char* pVl = (const char*)(Vlo + (size_t)(b * Tn) * Dn + h * 64);

    // stage layout: P 0 (32KB), Vh 32768, Vl 49152; stride 65536
    auto load_stage = [&](int jt, int stg) {
        uint32_t sb = sbase + (uint32_t)(stg * 65536);
        size_t pcol = (size_t)(jt * 128) * 2;
        #pragma unroll
        for (int i = 0; i < 8; i++) {
            int id = tid + 256 * i;
            int r = id >> 4, ck = id & 15;
            uint32_t soff = (uint32_t)(r * 256 + SWZ256(ck, r));
            size_t go = (size_t)r * ldp + pcol + (size_t)ck * 16;
            cp16(sb + soff, pP + go);
        }
        #pragma unroll
        for (int i = 0; i < 4; i++) {
            int id = tid + 256 * i;
            int r = id >> 3, ck = id & 7;
            uint32_t soff = (uint32_t)(r * 128 + SWZ128(ck, r));
            size_t go = (size_t)(jt * 128 + r) * ldv + (size_t)ck * 16;
            cp16(sb + 32768 + soff, pVh + go);
            cp16(sb + 49152 + soff, pVl + go);
        }
        cp_commit();
    };

    load_stage(0, 0);
    float acc[4][2][4] = {};

    for (int jt = 0; jt <= bi; jt++) {
        cp_wait<0>();
        __syncthreads();
        if (jt < bi) load_stage(jt + 1, (jt + 1) & 1);
        uint32_t base = sbase + (uint32_t)((jt & 1) * 65536);
        #pragma unroll
        for (int ks = 0; ks < 8; ks++) {
            uint32_t ah[4][4], bh[2][2], bl[2][2];
            #pragma unroll
            for (int mi = 0; mi < 4; mi++) {
                int r = wM * 64 + mi * 16 + (lane & 15);
                int chunk = ks * 2 + (lane >> 4);
                uint32_t ad = base + (uint32_t)(r * 256 + SWZ256(chunk, r));
                ldsm4(ah[mi], ad);
            }
            {
                int g = lane >> 3;
                int row = ks * 16 + ((g & 1) << 3) + (lane & 7);
                int chunk = wN * 2 + (g >> 1);
                uint32_t bd = base + 32768u +
                    (uint32_t)(row * 128 + SWZ128(chunk, row));
                uint32_t t0[4], t1[4];
                ldsm4t(t0, bd);
                ldsm4t(t1, bd + 16384u);
                bh[0][0] = t0[0]; bh[0][1] = t0[1];
                bh[1][0] = t0[2]; bh[1][1] = t0[3];
                bl[0][0] = t1[0]; bl[0][1] = t1[1];
                bl[1][0] = t1[2]; bl[1][1] = t1[3];
            }
            #pragma unroll
            for (int mi = 0; mi < 4; mi++)
                #pragma unroll
                for (int nj = 0; nj < 2; nj++)
                    mma16816(acc[mi][nj], ah[mi], bh[nj]);
            #pragma unroll
            for (int mi = 0; mi < 4; mi++)
                #pragma unroll
                for (int nj = 0; nj < 2; nj++)
                    mma16816(acc[mi][nj], ah[mi], bl[nj]);
        }
        __syncthreads();
    }

    const int rb = bi * 128 + wM * 64 + (lane >> 2);
    const int cb = wN * 16 + (lane & 3) * 2;
    #pragma unroll
    for (int mi = 0; mi < 4; mi++) {
        #pragma unroll
        for (int nj = 0; nj < 2; nj++) {
            int r0 = rb + mi * 16;
            int c = cb + nj * 8;
            float* a = acc[mi][nj];
            size_t off0 = ((size_t)(b * Tn) + r0) * Dn + h * 64 + c;
            size_t off1 = ((size_t)(b * Tn) + r0 + 8) * Dn + h * 64 + c;
            __half h0, l0, h1, l1;
            split2(a[0], h0, l0); split2(a[1], h1, l1);
            __half2 ph; ph.x = h0; ph.y = h1;
            __half2 pl; pl.x = l0; pl.y = l1;
            *(__half2*)(Ohi + off0) = ph;
            *(__half2*)(Olo + off0) = pl;
            split2(a[2], h0, l0); split2(a[3], h1, l1);
            ph.x = h0; ph.y = h1; pl.x = l0; pl.y = l1;
            *(__half2*)(Ohi + off1) = ph;
            *(__half2*)(Olo + off1) = pl;
        }
    }
}

// ---------------- launch ----------------
#define SMEM_GEMM (1024 + 3 * 49152)
#define SMEM_SC   (1024 + 49152)
#define SMEM_AV   (1024 + 2 * 65536)

extern "C" void kernel_launch(void* const* d_in, const int* in_sizes, int n_in,
                              void* d_out, int out_size) {
    const int*   ctx  = (const int*)  d_in[0];
    const float* tok  = (const float*)d_in[1];
    const float* pos  = (const float*)d_in[2];
    const float* Wq   = (const float*)d_in[3];
    const float* Wk   = (const float*)d_in[4];
    const float* Wv   = (const float*)d_in[5];
    const float* Wo   = (const float*)d_in[6];
    const float* bo   = (const float*)d_in[7];
    const float* ln1s = (const float*)d_in[8];
    const float* ln1b = (const float*)d_in[9];
    const float* W1   = (const float*)d_in[10];
    const float* b1   = (const float*)d_in[11];
    const float* W2   = (const float*)d_in[12];
    const float* b2   = (const float*)d_in[13];
    const float* ln2s = (const float*)d_in[14];
    const float* ln2b = (const float*)d_in[15];
    const float* lnfs = (const float*)d_in[16];
    const float* lnfb = (const float*)d_in[17];
    const float* Wout = (const float*)d_in[18];
    const float* bout = (const float*)d_in[19];
    float* out = (float*)d_out;

    float *x, *S;
    __half *hhi, *hlo, *qhi, *qlo, *khi, *vhi, *vlo;
    __half *ohi, *olo, *fhi, *flo, *phi;
    __half *wq, *wk, *wv, *wo, *w1, *w2, *wout;
    cudaGetSymbolAddress((void**)&x, g_x);
    cudaGetSymbolAddress((void**)&S, g_S);
    cudaGetSymbolAddress((void**)&phi, g_phi);
    cudaGetSymbolAddress((void**)&hhi, g_hhi);
    cudaGetSymbolAddress((void**)&hlo, g_hlo);
    cudaGetSymbolAddress((void**)&qhi, g_qhi);
    cudaGetSymbolAddress((void**)&qlo, g_qlo);
    cudaGetSymbolAddress((void**)&khi, g_khi);
    cudaGetSymbolAddress((void**)&vhi, g_vhi);
    cudaGetSymbolAddress((void**)&vlo, g_vlo);
    cudaGetSymbolAddress((void**)&ohi, g_ohi);
    cudaGetSymbolAddress((void**)&olo, g_olo);
    cudaGetSymbolAddress((void**)&fhi, g_fhi);
    cudaGetSymbolAddress((void**)&flo, g_flo);
    cudaGetSymbolAddress((void**)&wq, g_wqt);
    cudaGetSymbolAddress((void**)&wk, g_wkt);
    cudaGetSymbolAddress((void**)&wv, g_wvt);
    cudaGetSymbolAddress((void**)&wo, g_wot);
    cudaGetSymbolAddress((void**)&w1, g_w1t);
    cudaGetSymbolAddress((void**)&w2, g_w2t);
    cudaGetSymbolAddress((void**)&wout, g_woutt);

    cudaFuncSetAttribute(mmagemm<1>, cudaFuncAttributeMaxDynamicSharedMemorySize, SMEM_GEMM);
    cudaFuncSetAttribute(mmagemm<2>, cudaFuncAttributeMaxDynamicSharedMemorySize, SMEM_GEMM);
    cudaFuncSetAttribute(mmagemm<3>, cudaFuncAttributeMaxDynamicSharedMemorySize, SMEM_GEMM);
    cudaFuncSetAttribute(mmagemm<4>, cudaFuncAttributeMaxDynamicSharedMemorySize, SMEM_GEMM);
    cudaFuncSetAttribute(mmagemm<5>, cudaFuncAttributeMaxDynamicSharedMemorySize, SMEM_GEMM);
    cudaFuncSetAttribute(attn_scores_tc, cudaFuncAttributeMaxDynamicSharedMemorySize, SMEM_SC);
    cudaFuncSetAttribute(attn_av_tc, cudaFuncAttributeMaxDynamicSharedMemorySize, SMEM_AV);

    // weight prep (inside graph; deterministic)
    {
        dim3 blk(32, 8);
        dim3 gDD(Dn / 32, Dn / 32);
        dim3 gDF(Fn / 32, Dn / 32);
        dim3 gFD(Dn / 32, Fn / 32);
        dim3 gDV(Vn / 32, Dn / 32);
        for (int l = 0; l < NLAYER; l++) {
            size_t dd = (size_t)l * Dn * Dn;
            size_t df = (size_t)l * Dn * Fn;
            wconv_kernel<<<gDD, blk>>>(Wq + dd, wq + dd, Dn, Dn);
            wconv_kernel<<<gDD, blk>>>(Wk + dd, wk + dd, Dn, Dn);
            wconv_kernel<<<gDD, blk>>>(Wv + dd, wv + dd, Dn, Dn);
            wconv_kernel<<<gDD, blk>>>(Wo + dd, wo + dd, Dn, Dn);
            wconv_kernel<<<gDF, blk>>>(W1 + df, w1 + df, Dn, Fn);
            wconv_kernel<<<gFD, blk>>>(W2 + df, w2 + df, Fn, Dn);
        }
        wconv_kernel<<<gDV, blk>>>(Wout, wout, Dn, Vn);
    }

    embed_kernel<<<NROWS, 256>>>(ctx, tok, pos, x);

    dim3 gD(Dn / 128, NROWS / 128);     // (8, 32)
    dim3 gF(Fn / 128, NROWS / 128);     // (32, 32)
    dim3 gV(Vn / 128, NROWS / 128);     // (250, 32)
    dim3 gScore(Tn / 128, Tn / 128, Bn * Hn);
    dim3 gAV(Tn / 128, Bn * Hn);

    for (int l = 0; l < NLAYER; l++) {
        size_t dd = (size_t)l * Dn * Dn;
        size_t df = (size_t)l * Dn * Fn;

        ln_kernel<<<NROWS, 256>>>(x, ln1s + l * Dn, ln1b + l * Dn, hhi, hlo);
        mmagemm<4><<<gD, 256, SMEM_GEMM>>>(hhi, hlo, wq + dd,
                                           nullptr, nullptr, nullptr, qhi, qlo, Dn, Dn);
        mmagemm<5><<<gD, 256, SMEM_GEMM>>>(hhi, hlo, wk + dd,
                                           nullptr, nullptr, nullptr, khi, nullptr, Dn, Dn);
        mmagemm<4><<<gD, 256, SMEM_GEMM>>>(hhi, hlo, wv + dd,
                                           nullptr, nullptr, nullptr, vhi, vlo, Dn, Dn);

        attn_scores_tc<<<gScore, 256, SMEM_SC>>>(qhi, qlo, khi, S);
        softmax_kernel<<<Bn * Hn * Tn, 256>>>(S, phi);
        attn_av_tc<<<gAV, 256, SMEM_AV>>>(phi, vhi, vlo, ohi, olo);

        // x = x + o @ Wo + bo
        mmagemm<3><<<gD, 256, SMEM_GEMM>>>(ohi, olo, wo + dd,
                                           bo + l * Dn, x, x, nullptr, nullptr, Dn, Dn);

        ln_kernel<<<NROWS, 256>>>(x, ln2s + l * Dn, ln2b + l * Dn, hhi, hlo);
        // f = relu(h @ W1 + b1) -> fp16 hi/lo
        mmagemm<2><<<gF, 256, SMEM_GEMM>>>(hhi, hlo, w1 + df,
                                           b1 + l * Fn, nullptr, nullptr, fhi, flo, Fn, Dn);
        // x = x + f @ W2 + b2
        mmagemm<3><<<gD, 256, SMEM_GEMM>>>(fhi, flo, w2 + df,
                                           b2 + l * Dn, x, x, nullptr, nullptr, Dn, Fn);
    }

    ln_kernel<<<NROWS, 256>>>(x, lnfs, lnfb, hhi, hlo);
    mmagemm<1><<<gV, 256, SMEM_GEMM>>>(hhi, hlo, wout,
                                       bout, nullptr, out, nullptr, nullptr, Vn, Dn);
}